// round 2
// baseline (speedup 1.0000x reference)
#include <cuda_runtime.h>
#include <math.h>

// ---------------- problem constants ----------------
#define BB   4
#define SS   1024
#define SDIM 512
#define DD   1024
#define HH   16
#define LLAY 6
#define FFD  4096
#define AA   64
#define DKH  64
#define MTOT (BB*SS)          // 4096
#define EPS  1e-5f

// ---------------- scratch (static device allocations are the sanctioned path) ----------------
__device__ float g_x  [MTOT*DD];          // residual stream
__device__ float g_q  [MTOT*DD];
__device__ float g_k  [MTOT*DD];
__device__ float g_v  [MTOT*DD];
__device__ float g_ctx[MTOT*DD];
__device__ float g_t0 [MTOT*DD];          // attn_out / ff2 result
__device__ float g_ff [MTOT*FFD];         // relu(x@W1+b1)
__device__ float g_sc [(size_t)BB*HH*SS*SS]; // attention scores / probs (256 MB)

// ---------------- generic SGEMM: C = A[M,K] @ B[K,N] + bias[N] (+epilogue) ----------------
// EPI: 0 = bias, 1 = bias+relu, 2 = bias + pe[row%S, :]
// BM=BN=128, BK=8, 256 threads, 8x8 microtile. All dims divisible (asserted by shapes).
template<int EPI>
__global__ __launch_bounds__(256)
void sgemm_kernel(int M, int N, int K,
                  const float* __restrict__ A, const float* __restrict__ Bm,
                  const float* __restrict__ bias, const float* __restrict__ pe,
                  float* __restrict__ C)
{
    const int BM = 128, BN = 128, BK = 8, TM = 8, TN = 8;
    __shared__ float As[BK][BM];   // transposed A tile
    __shared__ float Bs[BK][BN];

    const int tid  = threadIdx.x;
    const int trow = tid >> 4;       // 0..15
    const int tcol = tid & 15;       // 0..15
    const int rowBase = blockIdx.y * BM;
    const int colBase = blockIdx.x * BN;

    // A tile loads: 128x8, float4 per thread-half
    const int aRow  = tid >> 1;           // 0..127
    const int aCol4 = (tid & 1) * 4;      // 0 or 4
    // B tile loads: 8x128, one float4 per thread
    const int bRow  = tid >> 5;           // 0..7
    const int bCol4 = (tid & 31) * 4;     // 0..124

    float acc[TM][TN];
    #pragma unroll
    for (int m = 0; m < TM; m++)
        #pragma unroll
        for (int n = 0; n < TN; n++) acc[m][n] = 0.f;

    for (int k0 = 0; k0 < K; k0 += BK) {
        float4 av = *reinterpret_cast<const float4*>(
            &A[(size_t)(rowBase + aRow) * K + k0 + aCol4]);
        As[aCol4 + 0][aRow] = av.x;
        As[aCol4 + 1][aRow] = av.y;
        As[aCol4 + 2][aRow] = av.z;
        As[aCol4 + 3][aRow] = av.w;
        *reinterpret_cast<float4*>(&Bs[bRow][bCol4]) =
            *reinterpret_cast<const float4*>(
                &Bm[(size_t)(k0 + bRow) * N + colBase + bCol4]);
        __syncthreads();

        #pragma unroll
        for (int k = 0; k < BK; k++) {
            float ra[TM], rb[TN];
            float4 a0 = *reinterpret_cast<const float4*>(&As[k][trow*TM]);
            float4 a1 = *reinterpret_cast<const float4*>(&As[k][trow*TM+4]);
            ra[0]=a0.x; ra[1]=a0.y; ra[2]=a0.z; ra[3]=a0.w;
            ra[4]=a1.x; ra[5]=a1.y; ra[6]=a1.z; ra[7]=a1.w;
            float4 b0 = *reinterpret_cast<const float4*>(&Bs[k][tcol*TN]);
            float4 b1 = *reinterpret_cast<const float4*>(&Bs[k][tcol*TN+4]);
            rb[0]=b0.x; rb[1]=b0.y; rb[2]=b0.z; rb[3]=b0.w;
            rb[4]=b1.x; rb[5]=b1.y; rb[6]=b1.z; rb[7]=b1.w;
            #pragma unroll
            for (int m = 0; m < TM; m++)
                #pragma unroll
                for (int n = 0; n < TN; n++)
                    acc[m][n] += ra[m] * rb[n];
        }
        __syncthreads();
    }

    #pragma unroll
    for (int m = 0; m < TM; m++) {
        const int row = rowBase + trow * TM + m;
        const float* perow = (EPI == 2) ? &pe[(size_t)(row & (SS - 1)) * N] : nullptr;
        #pragma unroll
        for (int n = 0; n < TN; n += 4) {
            const int col = colBase + tcol * TN + n;
            float4 bsv = *reinterpret_cast<const float4*>(&bias[col]);
            float4 o;
            o.x = acc[m][n+0] + bsv.x;
            o.y = acc[m][n+1] + bsv.y;
            o.z = acc[m][n+2] + bsv.z;
            o.w = acc[m][n+3] + bsv.w;
            if (EPI == 1) {
                o.x = fmaxf(o.x, 0.f); o.y = fmaxf(o.y, 0.f);
                o.z = fmaxf(o.z, 0.f); o.w = fmaxf(o.w, 0.f);
            }
            if (EPI == 2) {
                float4 p = *reinterpret_cast<const float4*>(&perow[col]);
                o.x += p.x; o.y += p.y; o.z += p.z; o.w += p.w;
            }
            *reinterpret_cast<float4*>(&C[(size_t)row * N + col]) = o;
        }
    }
}

// ---------------- scores = Q Kᵀ / sqrt(DK), batched over (b,h) ----------------
// grid: (S/64, S/64, B*H), 256 threads, 4x4 microtile, K=64 resident in smem (transposed).
__global__ __launch_bounds__(256)
void scores_kernel(const float* __restrict__ q, const float* __restrict__ kmat,
                   float* __restrict__ sc)
{
    __shared__ float Qs[64][65];   // [d][row]
    __shared__ float Ks[64][65];
    const int bh = blockIdx.z;
    const int b = bh >> 4, h = bh & 15;
    const float* qb = q    + (size_t)b * SS * DD + (size_t)h * DKH;
    const float* kb = kmat + (size_t)b * SS * DD + (size_t)h * DKH;
    const int q0 = blockIdx.y * 64, k0 = blockIdx.x * 64;
    const int tid = threadIdx.x;
    const int lr = tid >> 4, lc = (tid & 15) * 4;

    #pragma unroll
    for (int i = 0; i < 4; i++) {
        const int r = lr + i * 16;
        float4 qv = *reinterpret_cast<const float4*>(&qb[(size_t)(q0 + r) * DD + lc]);
        Qs[lc+0][r] = qv.x; Qs[lc+1][r] = qv.y; Qs[lc+2][r] = qv.z; Qs[lc+3][r] = qv.w;
        float4 kv = *reinterpret_cast<const float4*>(&kb[(size_t)(k0 + r) * DD + lc]);
        Ks[lc+0][r] = kv.x; Ks[lc+1][r] = kv.y; Ks[lc+2][r] = kv.z; Ks[lc+3][r] = kv.w;
    }
    __syncthreads();

    const int trow = tid >> 4, tcol = tid & 15;
    float acc[4][4];
    #pragma unroll
    for (int m = 0; m < 4; m++)
        #pragma unroll
        for (int n = 0; n < 4; n++) acc[m][n] = 0.f;

    #pragma unroll
    for (int d = 0; d < 64; d++) {
        float rq[4], rk[4];
        #pragma unroll
        for (int m = 0; m < 4; m++) rq[m] = Qs[d][trow*4+m];
        #pragma unroll
        for (int n = 0; n < 4; n++) rk[n] = Ks[d][tcol*4+n];
        #pragma unroll
        for (int m = 0; m < 4; m++)
            #pragma unroll
            for (int n = 0; n < 4; n++) acc[m][n] += rq[m]*rk[n];
    }

    float* scp = sc + (size_t)bh * SS * SS;
    #pragma unroll
    for (int m = 0; m < 4; m++) {
        float4 o;
        o.x = acc[m][0]*0.125f; o.y = acc[m][1]*0.125f;
        o.z = acc[m][2]*0.125f; o.w = acc[m][3]*0.125f;
        *reinterpret_cast<float4*>(
            &scp[(size_t)(q0 + trow*4 + m) * SS + k0 + tcol*4]) = o;
    }
}

// ---------------- row softmax over scores (in-place), one block per row ----------------
__global__ __launch_bounds__(256)
void softmax_kernel(float* __restrict__ sc)
{
    const size_t row = blockIdx.x;
    float* p = sc + row * SS;
    const int tid = threadIdx.x;
    float4 v = *reinterpret_cast<float4*>(&p[tid * 4]);

    __shared__ float sm[8];
    float m = fmaxf(fmaxf(v.x, v.y), fmaxf(v.z, v.w));
    #pragma unroll
    for (int o = 16; o; o >>= 1) m = fmaxf(m, __shfl_xor_sync(~0u, m, o));
    if ((tid & 31) == 0) sm[tid >> 5] = m;
    __syncthreads();
    float bm = sm[0];
    #pragma unroll
    for (int i = 1; i < 8; i++) bm = fmaxf(bm, sm[i]);
    __syncthreads();

    v.x = __expf(v.x - bm); v.y = __expf(v.y - bm);
    v.z = __expf(v.z - bm); v.w = __expf(v.w - bm);
    float s = v.x + v.y + v.z + v.w;
    #pragma unroll
    for (int o = 16; o; o >>= 1) s += __shfl_xor_sync(~0u, s, o);
    if ((tid & 31) == 0) sm[tid >> 5] = s;
    __syncthreads();
    float tot = 0.f;
    #pragma unroll
    for (int i = 0; i < 8; i++) tot += sm[i];
    const float inv = 1.f / tot;

    v.x *= inv; v.y *= inv; v.z *= inv; v.w *= inv;
    *reinterpret_cast<float4*>(&p[tid * 4]) = v;
}

// ---------------- ctx = attn @ V, batched over (b,h); N = DK = 64 ----------------
// grid: (S/64, B*H), 256 threads, 4x4 microtile.
__global__ __launch_bounds__(256)
void ctx_kernel(const float* __restrict__ sc, const float* __restrict__ v,
                float* __restrict__ ctx)
{
    __shared__ float As[64][64];
    __shared__ float Vs[64][64];
    const int bh = blockIdx.y;
    const int b = bh >> 4, h = bh & 15;
    const float* ap = sc + (size_t)bh * SS * SS;
    const float* vp = v  + (size_t)b * SS * DD + (size_t)h * DKH;
    const int q0 = blockIdx.x * 64;
    const int tid = threadIdx.x;
    const int lr = tid >> 4, lc = (tid & 15) * 4;
    const int trow = tid >> 4, tcol = tid & 15;

    float acc[4][4];
    #pragma unroll
    for (int m = 0; m < 4; m++)
        #pragma unroll
        for (int n = 0; n < 4; n++) acc[m][n] = 0.f;

    for (int kk = 0; kk < SS; kk += 64) {
        #pragma unroll
        for (int i = 0; i < 4; i++) {
            const int r = lr + i * 16;
            *reinterpret_cast<float4*>(&As[r][lc]) =
                *reinterpret_cast<const float4*>(&ap[(size_t)(q0 + r) * SS + kk + lc]);
            *reinterpret_cast<float4*>(&Vs[r][lc]) =
                *reinterpret_cast<const float4*>(&vp[(size_t)(kk + r) * DD + lc]);
        }
        __syncthreads();
        #pragma unroll
        for (int k = 0; k < 64; k++) {
            float ra[4], rv[4];
            #pragma unroll
            for (int m = 0; m < 4; m++) ra[m] = As[trow*4+m][k];
            #pragma unroll
            for (int n = 0; n < 4; n++) rv[n] = Vs[k][tcol*4+n];
            #pragma unroll
            for (int m = 0; m < 4; m++)
                #pragma unroll
                for (int n = 0; n < 4; n++) acc[m][n] += ra[m]*rv[n];
        }
        __syncthreads();
    }

    #pragma unroll
    for (int m = 0; m < 4; m++) {
        float4 o; o.x = acc[m][0]; o.y = acc[m][1]; o.z = acc[m][2]; o.w = acc[m][3];
        *reinterpret_cast<float4*>(
            &ctx[(size_t)(b*SS + q0 + trow*4 + m) * DD + h*DKH + tcol*4]) = o;
    }
}

// ---------------- x = LayerNorm(x + res) * gamma + beta, in place; one block per row --------
__global__ __launch_bounds__(256)
void add_ln_kernel(float* __restrict__ x, const float* __restrict__ res,
                   const float* __restrict__ gam, const float* __restrict__ bet)
{
    const int row = blockIdx.x;
    const int tid = threadIdx.x;
    float* px = x + (size_t)row * DD;
    const float* pr = res + (size_t)row * DD;

    float4 a = *reinterpret_cast<float4*>(&px[tid*4]);
    float4 r = *reinterpret_cast<const float4*>(&pr[tid*4]);
    a.x += r.x; a.y += r.y; a.z += r.z; a.w += r.w;

    float s  = a.x + a.y + a.z + a.w;
    float sq = a.x*a.x + a.y*a.y + a.z*a.z + a.w*a.w;
    __shared__ float sm[8], sm2[8];
    #pragma unroll
    for (int o = 16; o; o >>= 1) {
        s  += __shfl_xor_sync(~0u, s,  o);
        sq += __shfl_xor_sync(~0u, sq, o);
    }
    if ((tid & 31) == 0) { sm[tid>>5] = s; sm2[tid>>5] = sq; }
    __syncthreads();
    float ts = 0.f, tq = 0.f;
    #pragma unroll
    for (int i = 0; i < 8; i++) { ts += sm[i]; tq += sm2[i]; }
    const float mean = ts * (1.f / DD);
    const float var  = tq * (1.f / DD) - mean * mean;
    const float rstd = rsqrtf(var + EPS);

    float4 g = *reinterpret_cast<const float4*>(&gam[tid*4]);
    float4 b = *reinterpret_cast<const float4*>(&bet[tid*4]);
    float4 o;
    o.x = (a.x - mean) * rstd * g.x + b.x;
    o.y = (a.y - mean) * rstd * g.y + b.y;
    o.z = (a.z - mean) * rstd * g.z + b.z;
    o.w = (a.w - mean) * rstd * g.w + b.w;
    *reinterpret_cast<float4*>(&px[tid*4]) = o;
}

// ---------------- heads: policy (B*A outputs) + value (B outputs) ----------------
__global__ __launch_bounds__(256)
void head_kernel(const float* __restrict__ x,
                 const float* __restrict__ phw, const float* __restrict__ phb,
                 const float* __restrict__ vhw, const float* __restrict__ vhb,
                 float* __restrict__ out)
{
    const int o = blockIdx.x;           // 0..259
    const int tid = threadIdx.x;
    float acc = 0.f;
    float biasv;
    if (o < BB * AA) {
        const int b = o / AA, col = o % AA;
        const float* xr = x + (size_t)(b * SS + SS - 1) * DD;
        for (int d = tid; d < DD; d += 256) acc += xr[d] * phw[(size_t)d * AA + col];
        biasv = phb[col];
    } else {
        const int b = o - BB * AA;
        const float* xr = x + (size_t)(b * SS + SS - 1) * DD;
        for (int d = tid; d < DD; d += 256) acc += xr[d] * vhw[d];
        biasv = vhb[0];
    }
    __shared__ float sm[8];
    #pragma unroll
    for (int off = 16; off; off >>= 1) acc += __shfl_xor_sync(~0u, acc, off);
    if ((tid & 31) == 0) sm[tid >> 5] = acc;
    __syncthreads();
    if (tid == 0) {
        float t = 0.f;
        #pragma unroll
        for (int i = 0; i < 8; i++) t += sm[i];
        out[o] = t + biasv;
    }
}

// ---------------- host orchestration ----------------
extern "C" void kernel_launch(void* const* d_in, const int* in_sizes, int n_in,
                              void* d_out, int out_size)
{
    const float* states = (const float*)d_in[0];
    const float* pe     = (const float*)d_in[1];
    const float* emb_w  = (const float*)d_in[2];
    const float* emb_b  = (const float*)d_in[3];
    const float* Wq     = (const float*)d_in[4];
    const float* bq     = (const float*)d_in[5];
    const float* Wk     = (const float*)d_in[6];
    const float* bk     = (const float*)d_in[7];
    const float* Wv     = (const float*)d_in[8];
    const float* bv     = (const float*)d_in[9];
    const float* Wo     = (const float*)d_in[10];
    const float* bo     = (const float*)d_in[11];
    const float* ln1_s  = (const float*)d_in[12];
    const float* ln1_b  = (const float*)d_in[13];
    const float* ln2_s  = (const float*)d_in[14];
    const float* ln2_b  = (const float*)d_in[15];
    const float* ff_w1  = (const float*)d_in[16];
    const float* ff_b1  = (const float*)d_in[17];
    const float* ff_w2  = (const float*)d_in[18];
    const float* ff_b2  = (const float*)d_in[19];
    const float* vh_w   = (const float*)d_in[20];
    const float* vh_b   = (const float*)d_in[21];
    const float* ph_w   = (const float*)d_in[22];
    const float* ph_b   = (const float*)d_in[23];

    float *x, *q, *k, *v, *ctx, *t0, *ff, *sc;
    cudaGetSymbolAddress((void**)&x,   g_x);
    cudaGetSymbolAddress((void**)&q,   g_q);
    cudaGetSymbolAddress((void**)&k,   g_k);
    cudaGetSymbolAddress((void**)&v,   g_v);
    cudaGetSymbolAddress((void**)&ctx, g_ctx);
    cudaGetSymbolAddress((void**)&t0,  g_t0);
    cudaGetSymbolAddress((void**)&ff,  g_ff);
    cudaGetSymbolAddress((void**)&sc,  g_sc);

    const dim3 gemmD   (DD  / 128, MTOT / 128);   // (8, 32)
    const dim3 gemmFF  (FFD / 128, MTOT / 128);   // (32, 32)
    const dim3 gridSc  (SS / 64, SS / 64, BB * HH);
    const dim3 gridCtx (SS / 64, BB * HH);

    // embed: x = states @ emb_w + emb_b + pe
    sgemm_kernel<2><<<gemmD, 256>>>(MTOT, DD, SDIM, states, emb_w, emb_b, pe, x);

    for (int l = 0; l < LLAY; l++) {
        const size_t wofD = (size_t)l * DD * DD;
        const size_t wofF = (size_t)l * DD * FFD;

        sgemm_kernel<0><<<gemmD, 256>>>(MTOT, DD, DD, x, Wq + wofD, bq + (size_t)l*DD, nullptr, q);
        sgemm_kernel<0><<<gemmD, 256>>>(MTOT, DD, DD, x, Wk + wofD, bk + (size_t)l*DD, nullptr, k);
        sgemm_kernel<0><<<gemmD, 256>>>(MTOT, DD, DD, x, Wv + wofD, bv + (size_t)l*DD, nullptr, v);

        scores_kernel<<<gridSc, 256>>>(q, k, sc);
        softmax_kernel<<<BB * HH * SS, 256>>>(sc);
        ctx_kernel<<<gridCtx, 256>>>(sc, v, ctx);

        sgemm_kernel<0><<<gemmD, 256>>>(MTOT, DD, DD, ctx, Wo + wofD, bo + (size_t)l*DD, nullptr, t0);
        add_ln_kernel<<<MTOT, 256>>>(x, t0, ln1_s + (size_t)l*DD, ln1_b + (size_t)l*DD);

        sgemm_kernel<1><<<gemmFF, 256>>>(MTOT, FFD, DD, x, ff_w1 + wofF, ff_b1 + (size_t)l*FFD, nullptr, ff);
        sgemm_kernel<0><<<gemmD, 256>>>(MTOT, DD, FFD, ff, ff_w2 + wofF, ff_b2 + (size_t)l*DD, nullptr, t0);
        add_ln_kernel<<<MTOT, 256>>>(x, t0, ln2_s + (size_t)l*DD, ln2_b + (size_t)l*DD);
    }

    head_kernel<<<BB * AA + BB, 256>>>(x, ph_w, ph_b, vh_w, vh_b, (float*)d_out);
}

// round 3
// speedup vs baseline: 1.9473x; 1.9473x over previous
#include <cuda_runtime.h>
#include <math.h>
#include <stdint.h>

// ---------------- problem constants ----------------
#define BB   4
#define SS   1024
#define SDIM 512
#define DD   1024
#define HH   16
#define LLAY 6
#define FFD  4096
#define AA   64
#define DKH  64
#define MTOT (BB*SS)          // 4096
#define EPS  1e-5f

// ---------------- scratch ----------------
__device__ float g_x  [MTOT*DD];
__device__ float g_q  [MTOT*DD];
__device__ float g_k  [MTOT*DD];
__device__ float g_v  [MTOT*DD];
__device__ float g_ctx[MTOT*DD];
__device__ float g_t0 [MTOT*DD];
__device__ float g_ff [MTOT*FFD];
__device__ float g_sc [(size_t)BB*HH*SS*SS];

// ---------------- tf32 mma helpers ----------------
__device__ __forceinline__ uint32_t f2tf32(float f) {
    uint32_t r;
    asm("cvt.rna.tf32.f32 %0, %1;" : "=r"(r) : "f"(f));
    return r;
}

__device__ __forceinline__ void mma_tf32(float* c,
    uint32_t a0, uint32_t a1, uint32_t a2, uint32_t a3,
    uint32_t b0, uint32_t b1)
{
    asm volatile(
        "mma.sync.aligned.m16n8k8.row.col.f32.tf32.tf32.f32 "
        "{%0,%1,%2,%3}, {%4,%5,%6,%7}, {%8,%9}, {%0,%1,%2,%3};\n"
        : "+f"(c[0]), "+f"(c[1]), "+f"(c[2]), "+f"(c[3])
        : "r"(a0), "r"(a1), "r"(a2), "r"(a3), "r"(b0), "r"(b1));
}

__device__ __forceinline__ void cpa16(uint32_t smem, const void* g) {
    asm volatile("cp.async.cg.shared.global [%0], [%1], 16;\n" :: "r"(smem), "l"(g));
}
__device__ __forceinline__ void cpa_commit() {
    asm volatile("cp.async.commit_group;\n");
}
template<int N>
__device__ __forceinline__ void cpa_wait() {
    asm volatile("cp.async.wait_group %0;\n" :: "n"(N));
}

// ---------------- tensor-core SGEMM (tf32): C = A[M,K]@B[K,N] + bias (+epi) ---
// EPI: 0 = bias, 1 = bias+relu, 2 = bias + pe[row%S, :]
// 128x128 block, BK=16, 8 warps of 64x32, cp.async double buffer.
template<int EPI>
__global__ __launch_bounds__(256)
void tgemm_kernel(int M, int N, int K,
                  const float* __restrict__ A, const float* __restrict__ Bm,
                  const float* __restrict__ bias, const float* __restrict__ pe,
                  float* __restrict__ C)
{
    constexpr int AS_STRIDE = 20;   // 16 + 4 pad: conflict-free frag reads
    constexpr int BS_STRIDE = 136;  // 128 + 8 pad: conflict-free frag reads
    __shared__ float As[2][128 * AS_STRIDE];
    __shared__ float Bs[2][16 * BS_STRIDE];

    const int tid  = threadIdx.x;
    const int lane = tid & 31;
    const int warp = tid >> 5;
    const int warpM = warp & 1;     // 2 warps over M (64 rows each)
    const int warpN = warp >> 1;    // 4 warps over N (32 cols each)
    const int lr = lane >> 2;       // 0..7
    const int lc = lane & 3;        // 0..3
    const int rowBase = blockIdx.y * 128;
    const int colBase = blockIdx.x * 128;

    // gmem->smem load mapping
    const int aRow  = tid >> 1;            // 0..127
    const int aChk  = (tid & 1) * 2;       // {0,2}
    const int bRow  = tid >> 4;            // 0..15
    const int bChk  = (tid & 15) * 2;      // 0..30 even

    float c[4][4][4];
    #pragma unroll
    for (int mt = 0; mt < 4; mt++)
        #pragma unroll
        for (int nt = 0; nt < 4; nt++)
            #pragma unroll
            for (int i = 0; i < 4; i++) c[mt][nt][i] = 0.f;

    const float* gA = A + (size_t)(rowBase + aRow) * K;
    const float* gB = Bm + colBase;
    const uint32_t saBase0 = (uint32_t)__cvta_generic_to_shared(&As[0][aRow * AS_STRIDE]);
    const uint32_t saBase1 = (uint32_t)__cvta_generic_to_shared(&As[1][aRow * AS_STRIDE]);
    const uint32_t sbBase0 = (uint32_t)__cvta_generic_to_shared(&Bs[0][bRow * BS_STRIDE]);
    const uint32_t sbBase1 = (uint32_t)__cvta_generic_to_shared(&Bs[1][bRow * BS_STRIDE]);

    const int T = K >> 4;

    auto loadTile = [&](int t, int buf) {
        const uint32_t sa = buf ? saBase1 : saBase0;
        const uint32_t sb = buf ? sbBase1 : sbBase0;
        const float* ga = gA + t * 16;
        cpa16(sa + (aChk + 0) * 16, ga + (aChk + 0) * 4);
        cpa16(sa + (aChk + 1) * 16, ga + (aChk + 1) * 4);
        const float* gb = gB + (size_t)(t * 16 + bRow) * N;
        cpa16(sb + (bChk + 0) * 16, gb + (bChk + 0) * 4);
        cpa16(sb + (bChk + 1) * 16, gb + (bChk + 1) * 4);
        cpa_commit();
    };

    loadTile(0, 0);

    for (int t = 0; t < T; t++) {
        const int cur = t & 1;
        if (t + 1 < T) {
            loadTile(t + 1, cur ^ 1);
            cpa_wait<1>();
        } else {
            cpa_wait<0>();
        }
        __syncthreads();

        const float* as = As[cur];
        const float* bs = Bs[cur];
        #pragma unroll
        for (int k8 = 0; k8 < 16; k8 += 8) {
            uint32_t bf[4][2];
            #pragma unroll
            for (int nt = 0; nt < 4; nt++) {
                const int ncol = warpN * 32 + nt * 8 + lr;
                bf[nt][0] = f2tf32(bs[(k8 + lc) * BS_STRIDE + ncol]);
                bf[nt][1] = f2tf32(bs[(k8 + lc + 4) * BS_STRIDE + ncol]);
            }
            #pragma unroll
            for (int mt = 0; mt < 4; mt++) {
                const int mrow = warpM * 64 + mt * 16 + lr;
                uint32_t a0 = f2tf32(as[(mrow)     * AS_STRIDE + k8 + lc]);
                uint32_t a1 = f2tf32(as[(mrow + 8) * AS_STRIDE + k8 + lc]);
                uint32_t a2 = f2tf32(as[(mrow)     * AS_STRIDE + k8 + lc + 4]);
                uint32_t a3 = f2tf32(as[(mrow + 8) * AS_STRIDE + k8 + lc + 4]);
                #pragma unroll
                for (int nt = 0; nt < 4; nt++)
                    mma_tf32(c[mt][nt], a0, a1, a2, a3, bf[nt][0], bf[nt][1]);
            }
        }
        __syncthreads();
    }

    // epilogue
    #pragma unroll
    for (int mt = 0; mt < 4; mt++) {
        const int r0 = rowBase + warpM * 64 + mt * 16 + lr;
        #pragma unroll
        for (int nt = 0; nt < 4; nt++) {
            const int col = colBase + warpN * 32 + nt * 8 + lc * 2;
            const float b0 = bias[col], b1 = bias[col + 1];
            float v00 = c[mt][nt][0] + b0, v01 = c[mt][nt][1] + b1;
            float v10 = c[mt][nt][2] + b0, v11 = c[mt][nt][3] + b1;
            if (EPI == 1) {
                v00 = fmaxf(v00, 0.f); v01 = fmaxf(v01, 0.f);
                v10 = fmaxf(v10, 0.f); v11 = fmaxf(v11, 0.f);
            }
            if (EPI == 2) {
                const float* p0 = &pe[(size_t)(r0 & (SS - 1)) * N + col];
                const float* p1 = &pe[(size_t)((r0 + 8) & (SS - 1)) * N + col];
                v00 += p0[0]; v01 += p0[1];
                v10 += p1[0]; v11 += p1[1];
            }
            *reinterpret_cast<float2*>(&C[(size_t)r0 * N + col]) = make_float2(v00, v01);
            *reinterpret_cast<float2*>(&C[(size_t)(r0 + 8) * N + col]) = make_float2(v10, v11);
        }
    }
}

// ---------------- scores = Q Kᵀ / sqrt(DK), batched over (b,h) ----------------
__global__ __launch_bounds__(256)
void scores_kernel(const float* __restrict__ q, const float* __restrict__ kmat,
                   float* __restrict__ sc)
{
    __shared__ float Qs[64][65];
    __shared__ float Ks[64][65];
    const int bh = blockIdx.z;
    const int b = bh >> 4, h = bh & 15;
    const float* qb = q    + (size_t)b * SS * DD + (size_t)h * DKH;
    const float* kb = kmat + (size_t)b * SS * DD + (size_t)h * DKH;
    const int q0 = blockIdx.y * 64, k0 = blockIdx.x * 64;
    const int tid = threadIdx.x;
    const int lr = tid >> 4, lc = (tid & 15) * 4;

    #pragma unroll
    for (int i = 0; i < 4; i++) {
        const int r = lr + i * 16;
        float4 qv = *reinterpret_cast<const float4*>(&qb[(size_t)(q0 + r) * DD + lc]);
        Qs[lc+0][r] = qv.x; Qs[lc+1][r] = qv.y; Qs[lc+2][r] = qv.z; Qs[lc+3][r] = qv.w;
        float4 kv = *reinterpret_cast<const float4*>(&kb[(size_t)(k0 + r) * DD + lc]);
        Ks[lc+0][r] = kv.x; Ks[lc+1][r] = kv.y; Ks[lc+2][r] = kv.z; Ks[lc+3][r] = kv.w;
    }
    __syncthreads();

    const int trow = tid >> 4, tcol = tid & 15;
    float acc[4][4];
    #pragma unroll
    for (int m = 0; m < 4; m++)
        #pragma unroll
        for (int n = 0; n < 4; n++) acc[m][n] = 0.f;

    #pragma unroll
    for (int d = 0; d < 64; d++) {
        float rq[4], rk[4];
        #pragma unroll
        for (int m = 0; m < 4; m++) rq[m] = Qs[d][trow*4+m];
        #pragma unroll
        for (int n = 0; n < 4; n++) rk[n] = Ks[d][tcol*4+n];
        #pragma unroll
        for (int m = 0; m < 4; m++)
            #pragma unroll
            for (int n = 0; n < 4; n++) acc[m][n] += rq[m]*rk[n];
    }

    float* scp = sc + (size_t)bh * SS * SS;
    #pragma unroll
    for (int m = 0; m < 4; m++) {
        float4 o;
        o.x = acc[m][0]*0.125f; o.y = acc[m][1]*0.125f;
        o.z = acc[m][2]*0.125f; o.w = acc[m][3]*0.125f;
        *reinterpret_cast<float4*>(
            &scp[(size_t)(q0 + trow*4 + m) * SS + k0 + tcol*4]) = o;
    }
}

// ---------------- row softmax over scores (in-place) ----------------
__global__ __launch_bounds__(256)
void softmax_kernel(float* __restrict__ sc)
{
    const size_t row = blockIdx.x;
    float* p = sc + row * SS;
    const int tid = threadIdx.x;
    float4 v = *reinterpret_cast<float4*>(&p[tid * 4]);

    __shared__ float sm[8];
    float m = fmaxf(fmaxf(v.x, v.y), fmaxf(v.z, v.w));
    #pragma unroll
    for (int o = 16; o; o >>= 1) m = fmaxf(m, __shfl_xor_sync(~0u, m, o));
    if ((tid & 31) == 0) sm[tid >> 5] = m;
    __syncthreads();
    float bm = sm[0];
    #pragma unroll
    for (int i = 1; i < 8; i++) bm = fmaxf(bm, sm[i]);
    __syncthreads();

    v.x = __expf(v.x - bm); v.y = __expf(v.y - bm);
    v.z = __expf(v.z - bm); v.w = __expf(v.w - bm);
    float s = v.x + v.y + v.z + v.w;
    #pragma unroll
    for (int o = 16; o; o >>= 1) s += __shfl_xor_sync(~0u, s, o);
    if ((tid & 31) == 0) sm[tid >> 5] = s;
    __syncthreads();
    float tot = 0.f;
    #pragma unroll
    for (int i = 0; i < 8; i++) tot += sm[i];
    const float inv = 1.f / tot;

    v.x *= inv; v.y *= inv; v.z *= inv; v.w *= inv;
    *reinterpret_cast<float4*>(&p[tid * 4]) = v;
}

// ---------------- ctx = attn @ V, batched over (b,h) ----------------
__global__ __launch_bounds__(256)
void ctx_kernel(const float* __restrict__ sc, const float* __restrict__ v,
                float* __restrict__ ctx)
{
    __shared__ float As[64][64];
    __shared__ float Vs[64][64];
    const int bh = blockIdx.y;
    const int b = bh >> 4, h = bh & 15;
    const float* ap = sc + (size_t)bh * SS * SS;
    const float* vp = v  + (size_t)b * SS * DD + (size_t)h * DKH;
    const int q0 = blockIdx.x * 64;
    const int tid = threadIdx.x;
    const int lr = tid >> 4, lc = (tid & 15) * 4;
    const int trow = tid >> 4, tcol = tid & 15;

    float acc[4][4];
    #pragma unroll
    for (int m = 0; m < 4; m++)
        #pragma unroll
        for (int n = 0; n < 4; n++) acc[m][n] = 0.f;

    for (int kk = 0; kk < SS; kk += 64) {
        #pragma unroll
        for (int i = 0; i < 4; i++) {
            const int r = lr + i * 16;
            *reinterpret_cast<float4*>(&As[r][lc]) =
                *reinterpret_cast<const float4*>(&ap[(size_t)(q0 + r) * SS + kk + lc]);
            *reinterpret_cast<float4*>(&Vs[r][lc]) =
                *reinterpret_cast<const float4*>(&vp[(size_t)(kk + r) * DD + lc]);
        }
        __syncthreads();
        #pragma unroll
        for (int k = 0; k < 64; k++) {
            float ra[4], rv[4];
            #pragma unroll
            for (int m = 0; m < 4; m++) ra[m] = As[trow*4+m][k];
            #pragma unroll
            for (int n = 0; n < 4; n++) rv[n] = Vs[k][tcol*4+n];
            #pragma unroll
            for (int m = 0; m < 4; m++)
                #pragma unroll
                for (int n = 0; n < 4; n++) acc[m][n] += ra[m]*rv[n];
        }
        __syncthreads();
    }

    #pragma unroll
    for (int m = 0; m < 4; m++) {
        float4 o; o.x = acc[m][0]; o.y = acc[m][1]; o.z = acc[m][2]; o.w = acc[m][3];
        *reinterpret_cast<float4*>(
            &ctx[(size_t)(b*SS + q0 + trow*4 + m) * DD + h*DKH + tcol*4]) = o;
    }
}

// ---------------- x = LayerNorm(x + res) * gamma + beta, in place ----------------
__global__ __launch_bounds__(256)
void add_ln_kernel(float* __restrict__ x, const float* __restrict__ res,
                   const float* __restrict__ gam, const float* __restrict__ bet)
{
    const int row = blockIdx.x;
    const int tid = threadIdx.x;
    float* px = x + (size_t)row * DD;
    const float* pr = res + (size_t)row * DD;

    float4 a = *reinterpret_cast<float4*>(&px[tid*4]);
    float4 r = *reinterpret_cast<const float4*>(&pr[tid*4]);
    a.x += r.x; a.y += r.y; a.z += r.z; a.w += r.w;

    float s  = a.x + a.y + a.z + a.w;
    float sq = a.x*a.x + a.y*a.y + a.z*a.z + a.w*a.w;
    __shared__ float sm[8], sm2[8];
    #pragma unroll
    for (int o = 16; o; o >>= 1) {
        s  += __shfl_xor_sync(~0u, s,  o);
        sq += __shfl_xor_sync(~0u, sq, o);
    }
    if ((tid & 31) == 0) { sm[tid>>5] = s; sm2[tid>>5] = sq; }
    __syncthreads();
    float ts = 0.f, tq = 0.f;
    #pragma unroll
    for (int i = 0; i < 8; i++) { ts += sm[i]; tq += sm2[i]; }
    const float mean = ts * (1.f / DD);
    const float var  = tq * (1.f / DD) - mean * mean;
    const float rstd = rsqrtf(var + EPS);

    float4 g = *reinterpret_cast<const float4*>(&gam[tid*4]);
    float4 b = *reinterpret_cast<const float4*>(&bet[tid*4]);
    float4 o;
    o.x = (a.x - mean) * rstd * g.x + b.x;
    o.y = (a.y - mean) * rstd * g.y + b.y;
    o.z = (a.z - mean) * rstd * g.z + b.z;
    o.w = (a.w - mean) * rstd * g.w + b.w;
    *reinterpret_cast<float4*>(&px[tid*4]) = o;
}

// ---------------- heads ----------------
__global__ __launch_bounds__(256)
void head_kernel(const float* __restrict__ x,
                 const float* __restrict__ phw, const float* __restrict__ phb,
                 const float* __restrict__ vhw, const float* __restrict__ vhb,
                 float* __restrict__ out)
{
    const int o = blockIdx.x;
    const int tid = threadIdx.x;
    float acc = 0.f;
    float biasv;
    if (o < BB * AA) {
        const int b = o / AA, col = o % AA;
        const float* xr = x + (size_t)(b * SS + SS - 1) * DD;
        for (int d = tid; d < DD; d += 256) acc += xr[d] * phw[(size_t)d * AA + col];
        biasv = phb[col];
    } else {
        const int b = o - BB * AA;
        const float* xr = x + (size_t)(b * SS + SS - 1) * DD;
        for (int d = tid; d < DD; d += 256) acc += xr[d] * vhw[d];
        biasv = vhb[0];
    }
    __shared__ float sm[8];
    #pragma unroll
    for (int off = 16; off; off >>= 1) acc += __shfl_xor_sync(~0u, acc, off);
    if ((tid & 31) == 0) sm[tid >> 5] = acc;
    __syncthreads();
    if (tid == 0) {
        float t = 0.f;
        #pragma unroll
        for (int i = 0; i < 8; i++) t += sm[i];
        out[o] = t + biasv;
    }
}

// ---------------- host orchestration ----------------
extern "C" void kernel_launch(void* const* d_in, const int* in_sizes, int n_in,
                              void* d_out, int out_size)
{
    const float* states = (const float*)d_in[0];
    const float* pe     = (const float*)d_in[1];
    const float* emb_w  = (const float*)d_in[2];
    const float* emb_b  = (const float*)d_in[3];
    const float* Wq     = (const float*)d_in[4];
    const float* bq     = (const float*)d_in[5];
    const float* Wk     = (const float*)d_in[6];
    const float* bk     = (const float*)d_in[7];
    const float* Wv     = (const float*)d_in[8];
    const float* bv     = (const float*)d_in[9];
    const float* Wo     = (const float*)d_in[10];
    const float* bo     = (const float*)d_in[11];
    const float* ln1_s  = (const float*)d_in[12];
    const float* ln1_b  = (const float*)d_in[13];
    const float* ln2_s  = (const float*)d_in[14];
    const float* ln2_b  = (const float*)d_in[15];
    const float* ff_w1  = (const float*)d_in[16];
    const float* ff_b1  = (const float*)d_in[17];
    const float* ff_w2  = (const float*)d_in[18];
    const float* ff_b2  = (const float*)d_in[19];
    const float* vh_w   = (const float*)d_in[20];
    const float* vh_b   = (const float*)d_in[21];
    const float* ph_w   = (const float*)d_in[22];
    const float* ph_b   = (const float*)d_in[23];

    float *x, *q, *k, *v, *ctx, *t0, *ff, *sc;
    cudaGetSymbolAddress((void**)&x,   g_x);
    cudaGetSymbolAddress((void**)&q,   g_q);
    cudaGetSymbolAddress((void**)&k,   g_k);
    cudaGetSymbolAddress((void**)&v,   g_v);
    cudaGetSymbolAddress((void**)&ctx, g_ctx);
    cudaGetSymbolAddress((void**)&t0,  g_t0);
    cudaGetSymbolAddress((void**)&ff,  g_ff);
    cudaGetSymbolAddress((void**)&sc,  g_sc);

    const dim3 gemmD   (DD  / 128, MTOT / 128);   // (8, 32)
    const dim3 gemmFF  (FFD / 128, MTOT / 128);   // (32, 32)
    const dim3 gridSc  (SS / 64, SS / 64, BB * HH);
    const dim3 gridCtx (SS / 64, BB * HH);

    // embed: x = states @ emb_w + emb_b + pe
    tgemm_kernel<2><<<gemmD, 256>>>(MTOT, DD, SDIM, states, emb_w, emb_b, pe, x);

    for (int l = 0; l < LLAY; l++) {
        const size_t wofD = (size_t)l * DD * DD;
        const size_t wofF = (size_t)l * DD * FFD;

        tgemm_kernel<0><<<gemmD, 256>>>(MTOT, DD, DD, x, Wq + wofD, bq + (size_t)l*DD, nullptr, q);
        tgemm_kernel<0><<<gemmD, 256>>>(MTOT, DD, DD, x, Wk + wofD, bk + (size_t)l*DD, nullptr, k);
        tgemm_kernel<0><<<gemmD, 256>>>(MTOT, DD, DD, x, Wv + wofD, bv + (size_t)l*DD, nullptr, v);

        scores_kernel<<<gridSc, 256>>>(q, k, sc);
        softmax_kernel<<<BB * HH * SS, 256>>>(sc);
        ctx_kernel<<<gridCtx, 256>>>(sc, v, ctx);

        tgemm_kernel<0><<<gemmD, 256>>>(MTOT, DD, DD, ctx, Wo + wofD, bo + (size_t)l*DD, nullptr, t0);
        add_ln_kernel<<<MTOT, 256>>>(x, t0, ln1_s + (size_t)l*DD, ln1_b + (size_t)l*DD);

        tgemm_kernel<1><<<gemmFF, 256>>>(MTOT, FFD, DD, x, ff_w1 + wofF, ff_b1 + (size_t)l*FFD, nullptr, ff);
        tgemm_kernel<0><<<gemmD, 256>>>(MTOT, DD, FFD, ff, ff_w2 + wofF, ff_b2 + (size_t)l*DD, nullptr, t0);
        add_ln_kernel<<<MTOT, 256>>>(x, t0, ln2_s + (size_t)l*DD, ln2_b + (size_t)l*DD);
    }

    head_kernel<<<BB * AA + BB, 256>>>(x, ph_w, ph_b, vh_w, vh_b, (float*)d_out);
}

// round 5
// speedup vs baseline: 2.6832x; 1.3779x over previous
#include <cuda_runtime.h>
#include <math.h>
#include <stdint.h>

// ---------------- problem constants ----------------
#define BB   4
#define SS   1024
#define SDIM 512
#define DD   1024
#define HH   16
#define LLAY 6
#define FFD  4096
#define AA   64
#define DKH  64
#define MTOT (BB*SS)          // 4096
#define EPS  1e-5f

// ---------------- scratch ----------------
__device__ float g_x  [MTOT*DD];
__device__ float g_q  [MTOT*DD];
__device__ float g_k  [MTOT*DD];
__device__ float g_v  [MTOT*DD];
__device__ float g_ctx[MTOT*DD];
__device__ float g_t0 [MTOT*DD];
__device__ float g_ff [MTOT*FFD];

// ---------------- tf32 mma helpers ----------------
__device__ __forceinline__ uint32_t f2tf32(float f) {
    uint32_t r;
    asm("cvt.rna.tf32.f32 %0, %1;" : "=r"(r) : "f"(f));
    return r;
}
__device__ __forceinline__ float tff(float f) { return __uint_as_float(f2tf32(f)); }

__device__ __forceinline__ void mma_tf32(float* c,
    uint32_t a0, uint32_t a1, uint32_t a2, uint32_t a3,
    uint32_t b0, uint32_t b1)
{
    asm volatile(
        "mma.sync.aligned.m16n8k8.row.col.f32.tf32.tf32.f32 "
        "{%0,%1,%2,%3}, {%4,%5,%6,%7}, {%8,%9}, {%0,%1,%2,%3};\n"
        : "+f"(c[0]), "+f"(c[1]), "+f"(c[2]), "+f"(c[3])
        : "r"(a0), "r"(a1), "r"(a2), "r"(a3), "r"(b0), "r"(b1));
}

__device__ __forceinline__ void cpa16(uint32_t smem, const void* g) {
    asm volatile("cp.async.cg.shared.global [%0], [%1], 16;\n" :: "r"(smem), "l"(g));
}
__device__ __forceinline__ void cpa_commit() {
    asm volatile("cp.async.commit_group;\n");
}
template<int N>
__device__ __forceinline__ void cpa_wait() {
    asm volatile("cp.async.wait_group %0;\n" :: "n"(N));
}

// ---------------- tensor-core SGEMM (tf32): unchanged from R3 (proven) -------
template<int EPI>
__global__ __launch_bounds__(256)
void tgemm_kernel(int M, int N, int K,
                  const float* __restrict__ A, const float* __restrict__ Bm,
                  const float* __restrict__ bias, const float* __restrict__ pe,
                  float* __restrict__ C)
{
    constexpr int AS_STRIDE = 20;
    constexpr int BS_STRIDE = 136;
    __shared__ float As[2][128 * AS_STRIDE];
    __shared__ float Bs[2][16 * BS_STRIDE];

    const int tid  = threadIdx.x;
    const int lane = tid & 31;
    const int warp = tid >> 5;
    const int warpM = warp & 1;
    const int warpN = warp >> 1;
    const int lr = lane >> 2;
    const int lc = lane & 3;
    const int rowBase = blockIdx.y * 128;
    const int colBase = blockIdx.x * 128;

    const int aRow  = tid >> 1;
    const int aChk  = (tid & 1) * 2;
    const int bRow  = tid >> 4;
    const int bChk  = (tid & 15) * 2;

    float c[4][4][4];
    #pragma unroll
    for (int mt = 0; mt < 4; mt++)
        #pragma unroll
        for (int nt = 0; nt < 4; nt++)
            #pragma unroll
            for (int i = 0; i < 4; i++) c[mt][nt][i] = 0.f;

    const float* gA = A + (size_t)(rowBase + aRow) * K;
    const float* gB = Bm + colBase;
    const uint32_t saBase0 = (uint32_t)__cvta_generic_to_shared(&As[0][aRow * AS_STRIDE]);
    const uint32_t saBase1 = (uint32_t)__cvta_generic_to_shared(&As[1][aRow * AS_STRIDE]);
    const uint32_t sbBase0 = (uint32_t)__cvta_generic_to_shared(&Bs[0][bRow * BS_STRIDE]);
    const uint32_t sbBase1 = (uint32_t)__cvta_generic_to_shared(&Bs[1][bRow * BS_STRIDE]);

    const int T = K >> 4;

    auto loadTile = [&](int t, int buf) {
        const uint32_t sa = buf ? saBase1 : saBase0;
        const uint32_t sb = buf ? sbBase1 : sbBase0;
        const float* ga = gA + t * 16;
        cpa16(sa + (aChk + 0) * 16, ga + (aChk + 0) * 4);
        cpa16(sa + (aChk + 1) * 16, ga + (aChk + 1) * 4);
        const float* gb = gB + (size_t)(t * 16 + bRow) * N;
        cpa16(sb + (bChk + 0) * 16, gb + (bChk + 0) * 4);
        cpa16(sb + (bChk + 1) * 16, gb + (bChk + 1) * 4);
        cpa_commit();
    };

    loadTile(0, 0);

    for (int t = 0; t < T; t++) {
        const int cur = t & 1;
        if (t + 1 < T) {
            loadTile(t + 1, cur ^ 1);
            cpa_wait<1>();
        } else {
            cpa_wait<0>();
        }
        __syncthreads();

        const float* as = As[cur];
        const float* bs = Bs[cur];
        #pragma unroll
        for (int k8 = 0; k8 < 16; k8 += 8) {
            uint32_t bf[4][2];
            #pragma unroll
            for (int nt = 0; nt < 4; nt++) {
                const int ncol = warpN * 32 + nt * 8 + lr;
                bf[nt][0] = f2tf32(bs[(k8 + lc) * BS_STRIDE + ncol]);
                bf[nt][1] = f2tf32(bs[(k8 + lc + 4) * BS_STRIDE + ncol]);
            }
            #pragma unroll
            for (int mt = 0; mt < 4; mt++) {
                const int mrow = warpM * 64 + mt * 16 + lr;
                uint32_t a0 = f2tf32(as[(mrow)     * AS_STRIDE + k8 + lc]);
                uint32_t a1 = f2tf32(as[(mrow + 8) * AS_STRIDE + k8 + lc]);
                uint32_t a2 = f2tf32(as[(mrow)     * AS_STRIDE + k8 + lc + 4]);
                uint32_t a3 = f2tf32(as[(mrow + 8) * AS_STRIDE + k8 + lc + 4]);
                #pragma unroll
                for (int nt = 0; nt < 4; nt++)
                    mma_tf32(c[mt][nt], a0, a1, a2, a3, bf[nt][0], bf[nt][1]);
            }
        }
        __syncthreads();
    }

    #pragma unroll
    for (int mt = 0; mt < 4; mt++) {
        const int r0 = rowBase + warpM * 64 + mt * 16 + lr;
        #pragma unroll
        for (int nt = 0; nt < 4; nt++) {
            const int col = colBase + warpN * 32 + nt * 8 + lc * 2;
            const float b0 = bias[col], b1 = bias[col + 1];
            float v00 = c[mt][nt][0] + b0, v01 = c[mt][nt][1] + b1;
            float v10 = c[mt][nt][2] + b0, v11 = c[mt][nt][3] + b1;
            if (EPI == 1) {
                v00 = fmaxf(v00, 0.f); v01 = fmaxf(v01, 0.f);
                v10 = fmaxf(v10, 0.f); v11 = fmaxf(v11, 0.f);
            }
            if (EPI == 2) {
                const float* p0 = &pe[(size_t)(r0 & (SS - 1)) * N + col];
                const float* p1 = &pe[(size_t)((r0 + 8) & (SS - 1)) * N + col];
                v00 += p0[0]; v01 += p0[1];
                v10 += p1[0]; v11 += p1[1];
            }
            *reinterpret_cast<float2*>(&C[(size_t)r0 * N + col]) = make_float2(v00, v01);
            *reinterpret_cast<float2*>(&C[(size_t)(r0 + 8) * N + col]) = make_float2(v10, v11);
        }
    }
}

// ---------------- fused flash attention (tf32 mma, fp32 online softmax) -------
// grid = (S/64, B*H); block = 256 (8 warps: 4 row-groups x 2 col-groups).
// Static smem only (36.8KB): the 64x68 buffer is time-multiplexed
//   Q-staging -> K tile -> P tile   (phases separated by __syncthreads()).
// Strides: KP = 68 (banks 4*lr+lc conflict-free), V = 72 (banks 8*lc+lr).
#define KSTR 68
#define VSTR 72

__global__ __launch_bounds__(256)
void fattn_kernel(const float* __restrict__ q, const float* __restrict__ k,
                  const float* __restrict__ v, float* __restrict__ ctx)
{
    __shared__ float KP[64 * KSTR];   // Q staging, then K tile, then P tile
    __shared__ float Vs[64 * VSTR];
    __shared__ float Mred[4][2][16];
    __shared__ float Lred[4][2][16];

    const int tid   = threadIdx.x;
    const int lane  = tid & 31;
    const int warp  = tid >> 5;
    const int warpR = warp >> 1;          // 0..3 : 16-row group
    const int warpC = warp & 1;           // 0..1 : 32-col group
    const int lr    = lane >> 2;          // 0..7
    const int lc    = lane & 3;           // 0..3

    const int bh = blockIdx.y;
    const int b  = bh >> 4, h = bh & 15;
    const int q0 = blockIdx.x * 64;
    const float* qb = q + (size_t)b * SS * DD + (size_t)h * DKH;
    const float* kb = k + (size_t)b * SS * DD + (size_t)h * DKH;
    const float* vb = v + (size_t)b * SS * DD + (size_t)h * DKH;

    // tile loader mapping: each thread loads 4 float4 (row = tid/4)
    const int lrow = tid >> 2;
    const int lcl  = (tid & 3) * 4;

    // ---- stage Q tile into KP (tf32), pull fragments to registers ----
    {
        const float* qr = qb + (size_t)(q0 + lrow) * DD;
        #pragma unroll
        for (int j = 0; j < 4; j++) {
            float4 t = *reinterpret_cast<const float4*>(qr + lcl + j * 16);
            *reinterpret_cast<float4*>(&KP[lrow * KSTR + lcl + j * 16]) =
                make_float4(tff(t.x), tff(t.y), tff(t.z), tff(t.w));
        }
    }
    __syncthreads();

    const int r0 = warpR * 16 + lr;
    uint32_t qf[8][4];
    #pragma unroll
    for (int kk = 0; kk < 8; kk++) {
        qf[kk][0] = __float_as_uint(KP[(r0)     * KSTR + kk * 8 + lc]);
        qf[kk][1] = __float_as_uint(KP[(r0 + 8) * KSTR + kk * 8 + lc]);
        qf[kk][2] = __float_as_uint(KP[(r0)     * KSTR + kk * 8 + lc + 4]);
        qf[kk][3] = __float_as_uint(KP[(r0 + 8) * KSTR + kk * 8 + lc + 4]);
    }
    __syncthreads();   // all Q fragments read before KP is reused for K

    float o[4][4];
    #pragma unroll
    for (int nt = 0; nt < 4; nt++)
        #pragma unroll
        for (int i = 0; i < 4; i++) o[nt][i] = 0.f;
    float mrun0 = -INFINITY, mrun1 = -INFINITY;
    float lrun0 = 0.f, lrun1 = 0.f;

    for (int t = 0; t < 16; t++) {
        // ---- stage K -> KP, V -> Vs (fp32 -> tf32) ----
        {
            const float* kr = kb + (size_t)(t * 64 + lrow) * DD;
            const float* vr = vb + (size_t)(t * 64 + lrow) * DD;
            #pragma unroll
            for (int j = 0; j < 4; j++) {
                float4 tk = *reinterpret_cast<const float4*>(kr + lcl + j * 16);
                *reinterpret_cast<float4*>(&KP[lrow * KSTR + lcl + j * 16]) =
                    make_float4(tff(tk.x), tff(tk.y), tff(tk.z), tff(tk.w));
                float4 tv = *reinterpret_cast<const float4*>(vr + lcl + j * 16);
                *reinterpret_cast<float4*>(&Vs[lrow * VSTR + lcl + j * 16]) =
                    make_float4(tff(tv.x), tff(tv.y), tff(tv.z), tff(tv.w));
            }
        }
        __syncthreads();                                   // (1) K,V visible

        // ---- S = Q K^T (warp tile 16x32) ----
        float s[4][4];
        #pragma unroll
        for (int nt = 0; nt < 4; nt++)
            #pragma unroll
            for (int i = 0; i < 4; i++) s[nt][i] = 0.f;

        #pragma unroll
        for (int kk = 0; kk < 8; kk++) {
            #pragma unroll
            for (int nt = 0; nt < 4; nt++) {
                const int srow = warpC * 32 + nt * 8 + lr;
                uint32_t b0 = __float_as_uint(KP[srow * KSTR + kk * 8 + lc]);
                uint32_t b1 = __float_as_uint(KP[srow * KSTR + kk * 8 + lc + 4]);
                mma_tf32(s[nt], qf[kk][0], qf[kk][1], qf[kk][2], qf[kk][3], b0, b1);
            }
        }
        #pragma unroll
        for (int nt = 0; nt < 4; nt++)
            #pragma unroll
            for (int i = 0; i < 4; i++) s[nt][i] *= 0.125f;

        // ---- row max (intra-warp then cross-warpC) ----
        float m0 = -INFINITY, m1 = -INFINITY;
        #pragma unroll
        for (int nt = 0; nt < 4; nt++) {
            m0 = fmaxf(m0, fmaxf(s[nt][0], s[nt][1]));
            m1 = fmaxf(m1, fmaxf(s[nt][2], s[nt][3]));
        }
        m0 = fmaxf(m0, __shfl_xor_sync(~0u, m0, 1));
        m0 = fmaxf(m0, __shfl_xor_sync(~0u, m0, 2));
        m1 = fmaxf(m1, __shfl_xor_sync(~0u, m1, 1));
        m1 = fmaxf(m1, __shfl_xor_sync(~0u, m1, 2));
        if (lc == 0) { Mred[warpR][warpC][lr] = m0; Mred[warpR][warpC][lr + 8] = m1; }
        __syncthreads();         // (2) Mred visible; ALL S-mma done reading KP
        const float mt0 = fmaxf(Mred[warpR][0][lr],     Mred[warpR][1][lr]);
        const float mt1 = fmaxf(Mred[warpR][0][lr + 8], Mred[warpR][1][lr + 8]);

        const float mn0 = fmaxf(mrun0, mt0);
        const float mn1 = fmaxf(mrun1, mt1);
        const float a0 = __expf(mrun0 - mn0);
        const float a1 = __expf(mrun1 - mn1);
        mrun0 = mn0; mrun1 = mn1;

        // ---- P = exp(S - m); store P (tf32) into KP; row sums ----
        float ls0 = 0.f, ls1 = 0.f;
        #pragma unroll
        for (int nt = 0; nt < 4; nt++) {
            s[nt][0] = __expf(s[nt][0] - mn0);
            s[nt][1] = __expf(s[nt][1] - mn0);
            s[nt][2] = __expf(s[nt][2] - mn1);
            s[nt][3] = __expf(s[nt][3] - mn1);
            ls0 += s[nt][0] + s[nt][1];
            ls1 += s[nt][2] + s[nt][3];
            const int pc = warpC * 32 + nt * 8 + 2 * lc;
            *reinterpret_cast<float2*>(&KP[(r0)     * KSTR + pc]) =
                make_float2(tff(s[nt][0]), tff(s[nt][1]));
            *reinterpret_cast<float2*>(&KP[(r0 + 8) * KSTR + pc]) =
                make_float2(tff(s[nt][2]), tff(s[nt][3]));
            o[nt][0] *= a0; o[nt][1] *= a0;
            o[nt][2] *= a1; o[nt][3] *= a1;
        }
        ls0 += __shfl_xor_sync(~0u, ls0, 1);
        ls0 += __shfl_xor_sync(~0u, ls0, 2);
        ls1 += __shfl_xor_sync(~0u, ls1, 1);
        ls1 += __shfl_xor_sync(~0u, ls1, 2);
        if (lc == 0) { Lred[warpR][warpC][lr] = ls0; Lred[warpR][warpC][lr + 8] = ls1; }
        __syncthreads();                                   // (3) P + Lred visible
        lrun0 = lrun0 * a0 + Lred[warpR][0][lr]     + Lred[warpR][1][lr];
        lrun1 = lrun1 * a1 + Lred[warpR][0][lr + 8] + Lred[warpR][1][lr + 8];

        // ---- O += P V (warp tile 16 rows x 32 d-cols) ----
        #pragma unroll
        for (int kk = 0; kk < 8; kk++) {
            uint32_t pa0 = __float_as_uint(KP[(r0)     * KSTR + kk * 8 + lc]);
            uint32_t pa1 = __float_as_uint(KP[(r0 + 8) * KSTR + kk * 8 + lc]);
            uint32_t pa2 = __float_as_uint(KP[(r0)     * KSTR + kk * 8 + lc + 4]);
            uint32_t pa3 = __float_as_uint(KP[(r0 + 8) * KSTR + kk * 8 + lc + 4]);
            #pragma unroll
            for (int nt = 0; nt < 4; nt++) {
                const int dcol = warpC * 32 + nt * 8 + lr;
                uint32_t b0 = __float_as_uint(Vs[(kk * 8 + lc)     * VSTR + dcol]);
                uint32_t b1 = __float_as_uint(Vs[(kk * 8 + lc + 4) * VSTR + dcol]);
                mma_tf32(o[nt], pa0, pa1, pa2, pa3, b0, b1);
            }
        }
        __syncthreads();                 // (4) KP/Vs free for next tile
    }

    // ---- normalize and write ctx ----
    const float inv0 = 1.f / lrun0;
    const float inv1 = 1.f / lrun1;
    float* cb = ctx + (size_t)(b * SS + q0) * DD + h * DKH;
    #pragma unroll
    for (int nt = 0; nt < 4; nt++) {
        const int dcol = warpC * 32 + nt * 8 + 2 * lc;
        *reinterpret_cast<float2*>(&cb[(size_t)(r0)     * DD + dcol]) =
            make_float2(o[nt][0] * inv0, o[nt][1] * inv0);
        *reinterpret_cast<float2*>(&cb[(size_t)(r0 + 8) * DD + dcol]) =
            make_float2(o[nt][2] * inv1, o[nt][3] * inv1);
    }
}

// ---------------- x = LayerNorm(x + res) * gamma + beta, in place ----------------
__global__ __launch_bounds__(256)
void add_ln_kernel(float* __restrict__ x, const float* __restrict__ res,
                   const float* __restrict__ gam, const float* __restrict__ bet)
{
    const int row = blockIdx.x;
    const int tid = threadIdx.x;
    float* px = x + (size_t)row * DD;
    const float* pr = res + (size_t)row * DD;

    float4 a = *reinterpret_cast<float4*>(&px[tid*4]);
    float4 r = *reinterpret_cast<const float4*>(&pr[tid*4]);
    a.x += r.x; a.y += r.y; a.z += r.z; a.w += r.w;

    float s  = a.x + a.y + a.z + a.w;
    float sq = a.x*a.x + a.y*a.y + a.z*a.z + a.w*a.w;
    __shared__ float sm[8], sm2[8];
    #pragma unroll
    for (int o = 16; o; o >>= 1) {
        s  += __shfl_xor_sync(~0u, s,  o);
        sq += __shfl_xor_sync(~0u, sq, o);
    }
    if ((tid & 31) == 0) { sm[tid>>5] = s; sm2[tid>>5] = sq; }
    __syncthreads();
    float ts = 0.f, tq = 0.f;
    #pragma unroll
    for (int i = 0; i < 8; i++) { ts += sm[i]; tq += sm2[i]; }
    const float mean = ts * (1.f / DD);
    const float var  = tq * (1.f / DD) - mean * mean;
    const float rstd = rsqrtf(var + EPS);

    float4 g = *reinterpret_cast<const float4*>(&gam[tid*4]);
    float4 b = *reinterpret_cast<const float4*>(&bet[tid*4]);
    float4 o;
    o.x = (a.x - mean) * rstd * g.x + b.x;
    o.y = (a.y - mean) * rstd * g.y + b.y;
    o.z = (a.z - mean) * rstd * g.z + b.z;
    o.w = (a.w - mean) * rstd * g.w + b.w;
    *reinterpret_cast<float4*>(&px[tid*4]) = o;
}

// ---------------- heads ----------------
__global__ __launch_bounds__(256)
void head_kernel(const float* __restrict__ x,
                 const float* __restrict__ phw, const float* __restrict__ phb,
                 const float* __restrict__ vhw, const float* __restrict__ vhb,
                 float* __restrict__ out)
{
    const int o = blockIdx.x;
    const int tid = threadIdx.x;
    float acc = 0.f;
    float biasv;
    if (o < BB * AA) {
        const int b = o / AA, col = o % AA;
        const float* xr = x + (size_t)(b * SS + SS - 1) * DD;
        for (int d = tid; d < DD; d += 256) acc += xr[d] * phw[(size_t)d * AA + col];
        biasv = phb[col];
    } else {
        const int b = o - BB * AA;
        const float* xr = x + (size_t)(b * SS + SS - 1) * DD;
        for (int d = tid; d < DD; d += 256) acc += xr[d] * vhw[d];
        biasv = vhb[0];
    }
    __shared__ float sm[8];
    #pragma unroll
    for (int off = 16; off; off >>= 1) acc += __shfl_xor_sync(~0u, acc, off);
    if ((tid & 31) == 0) sm[tid >> 5] = acc;
    __syncthreads();
    if (tid == 0) {
        float t = 0.f;
        #pragma unroll
        for (int i = 0; i < 8; i++) t += sm[i];
        out[o] = t + biasv;
    }
}

// ---------------- host orchestration ----------------
extern "C" void kernel_launch(void* const* d_in, const int* in_sizes, int n_in,
                              void* d_out, int out_size)
{
    const float* states = (const float*)d_in[0];
    const float* pe     = (const float*)d_in[1];
    const float* emb_w  = (const float*)d_in[2];
    const float* emb_b  = (const float*)d_in[3];
    const float* Wq     = (const float*)d_in[4];
    const float* bq     = (const float*)d_in[5];
    const float* Wk     = (const float*)d_in[6];
    const float* bk     = (const float*)d_in[7];
    const float* Wv     = (const float*)d_in[8];
    const float* bv     = (const float*)d_in[9];
    const float* Wo     = (const float*)d_in[10];
    const float* bo     = (const float*)d_in[11];
    const float* ln1_s  = (const float*)d_in[12];
    const float* ln1_b  = (const float*)d_in[13];
    const float* ln2_s  = (const float*)d_in[14];
    const float* ln2_b  = (const float*)d_in[15];
    const float* ff_w1  = (const float*)d_in[16];
    const float* ff_b1  = (const float*)d_in[17];
    const float* ff_w2  = (const float*)d_in[18];
    const float* ff_b2  = (const float*)d_in[19];
    const float* vh_w   = (const float*)d_in[20];
    const float* vh_b   = (const float*)d_in[21];
    const float* ph_w   = (const float*)d_in[22];
    const float* ph_b   = (const float*)d_in[23];

    float *x, *q, *k, *v, *ctx, *t0, *ff;
    cudaGetSymbolAddress((void**)&x,   g_x);
    cudaGetSymbolAddress((void**)&q,   g_q);
    cudaGetSymbolAddress((void**)&k,   g_k);
    cudaGetSymbolAddress((void**)&v,   g_v);
    cudaGetSymbolAddress((void**)&ctx, g_ctx);
    cudaGetSymbolAddress((void**)&t0,  g_t0);
    cudaGetSymbolAddress((void**)&ff,  g_ff);

    const dim3 gemmD   (DD  / 128, MTOT / 128);   // (8, 32)
    const dim3 gemmFF  (FFD / 128, MTOT / 128);   // (32, 32)
    const dim3 gridAtt (SS / 64, BB * HH);        // (16, 64)

    // embed: x = states @ emb_w + emb_b + pe
    tgemm_kernel<2><<<gemmD, 256>>>(MTOT, DD, SDIM, states, emb_w, emb_b, pe, x);

    for (int l = 0; l < LLAY; l++) {
        const size_t wofD = (size_t)l * DD * DD;
        const size_t wofF = (size_t)l * DD * FFD;

        tgemm_kernel<0><<<gemmD, 256>>>(MTOT, DD, DD, x, Wq + wofD, bq + (size_t)l*DD, nullptr, q);
        tgemm_kernel<0><<<gemmD, 256>>>(MTOT, DD, DD, x, Wk + wofD, bk + (size_t)l*DD, nullptr, k);
        tgemm_kernel<0><<<gemmD, 256>>>(MTOT, DD, DD, x, Wv + wofD, bv + (size_t)l*DD, nullptr, v);

        fattn_kernel<<<gridAtt, 256>>>(q, k, v, ctx);

        tgemm_kernel<0><<<gemmD, 256>>>(MTOT, DD, DD, ctx, Wo + wofD, bo + (size_t)l*DD, nullptr, t0);
        add_ln_kernel<<<MTOT, 256>>>(x, t0, ln1_s + (size_t)l*DD, ln1_b + (size_t)l*DD);

        tgemm_kernel<1><<<gemmFF, 256>>>(MTOT, FFD, DD, x, ff_w1 + wofF, ff_b1 + (size_t)l*FFD, nullptr, ff);
        tgemm_kernel<0><<<gemmD, 256>>>(MTOT, DD, FFD, ff, ff_w2 + wofF, ff_b2 + (size_t)l*DD, nullptr, t0);
        add_ln_kernel<<<MTOT, 256>>>(x, t0, ln2_s + (size_t)l*DD, ln2_b + (size_t)l*DD);
    }

    head_kernel<<<BB * AA + BB, 256>>>(x, ph_w, ph_b, vh_w, vh_b, (float*)d_out);
}

// round 6
// speedup vs baseline: 2.8131x; 1.0484x over previous
#include <cuda_runtime.h>
#include <math.h>
#include <stdint.h>

// ---------------- problem constants ----------------
#define BB   4
#define SS   1024
#define SDIM 512
#define DD   1024
#define HH   16
#define LLAY 6
#define FFD  4096
#define AA   64
#define DKH  64
#define MTOT (BB*SS)          // 4096
#define EPS  1e-5f

// ---------------- scratch ----------------
__device__ float g_x  [MTOT*DD];
__device__ float g_q  [MTOT*DD];
__device__ float g_k  [MTOT*DD];
__device__ float g_v  [MTOT*DD];
__device__ float g_ctx[MTOT*DD];
__device__ float g_t0 [MTOT*DD];
__device__ float g_ff [MTOT*FFD];

// ---------------- tf32 mma helpers ----------------
__device__ __forceinline__ uint32_t f2tf32(float f) {
    uint32_t r;
    asm("cvt.rna.tf32.f32 %0, %1;" : "=r"(r) : "f"(f));
    return r;
}
__device__ __forceinline__ float tff(float f) { return __uint_as_float(f2tf32(f)); }

__device__ __forceinline__ void mma_tf32(float* c,
    uint32_t a0, uint32_t a1, uint32_t a2, uint32_t a3,
    uint32_t b0, uint32_t b1)
{
    asm volatile(
        "mma.sync.aligned.m16n8k8.row.col.f32.tf32.tf32.f32 "
        "{%0,%1,%2,%3}, {%4,%5,%6,%7}, {%8,%9}, {%0,%1,%2,%3};\n"
        : "+f"(c[0]), "+f"(c[1]), "+f"(c[2]), "+f"(c[3])
        : "r"(a0), "r"(a1), "r"(a2), "r"(a3), "r"(b0), "r"(b1));
}

// ---------------- tensor-core SGEMM (tf32), fragment-packed smem -------------
// C = A[M,K]@B[K,N] + bias (+epi). EPI: 0=bias, 1=bias+relu, 2=bias+pe.
// 128x128 block, BK=16, 8 warps (2 M x 4 N), warp tile 64x32.
// smem A: [buf][S=g*2+k8][32 slots][4 floats]  (fragment quads, LDS.128)
//   slot = lr*4+lc, swizzle pslot = slot ^ (lr>>1); quad = {a0,a1,a2,a3}
// smem B: [buf][S=cg*2+k8][32 slots][2 floats] (fragment pairs, LDS.64)
//   swizzle pslot = slot ^ (cg&15); pair = {b0,b1}
// Staging: LDG->regs (prefetch next tile) -> cvt tf32 -> STS. No inner-loop cvt.
template<int EPI>
__global__ __launch_bounds__(256, 2)
void tgemm_kernel(int M, int N, int K,
                  const float* __restrict__ A, const float* __restrict__ Bm,
                  const float* __restrict__ bias, const float* __restrict__ pe,
                  float* __restrict__ C)
{
    __shared__ float As2[2][2048];   // 8KB per buf
    __shared__ float Bs2[2][2048];

    const int tid  = threadIdx.x;
    const int lane = tid & 31;
    const int warp = tid >> 5;
    const int warpM = warp & 1;
    const int warpN = warp >> 1;
    const int lr = lane >> 2;
    const int lc = lane & 3;
    const int rowBase = blockIdx.y * 128;
    const int colBase = blockIdx.x * 128;

    // ---- staging thread mapping ----
    // A: row aRow (0..127), k-chunk aK8*8 .. +7
    const int aRow = tid >> 1;
    const int aK8  = tid & 1;
    // B: k-row bK (0..15), col-chunk bCg*8 .. +7
    const int bK   = tid >> 4;
    const int bCg  = tid & 15;

    // precomputed staging store constants
    const int aG    = aRow >> 4;
    const int aLr   = aRow & 7;
    const int aHalf = (aRow >> 3) & 1;
    const int aKey  = aLr >> 1;
    const int aSbase = (aG * 2 + aK8) * 32;        // slot-group base (A)
    const int bK8   = bK >> 3;
    const int bKk   = bK & 7;
    const int bLc   = bKk & 3;
    const int bHalf = bKk >> 2;
    const int bSbase = (bCg * 2 + bK8) * 32;       // slot-group base (B)

    // compute-side constants
    const int pslotA = (lr * 4 + lc) ^ (lr >> 1);  // bijection, conflict-free

    float c[4][4][4];
    #pragma unroll
    for (int mt = 0; mt < 4; mt++)
        #pragma unroll
        for (int nt = 0; nt < 4; nt++)
            #pragma unroll
            for (int i = 0; i < 4; i++) c[mt][nt][i] = 0.f;

    const float* gA = A + (size_t)(rowBase + aRow) * K + aK8 * 8;
    const float* gB = Bm + colBase + bCg * 8;

    const int T = K >> 4;

    float ar[8], br[8];

    auto loadRegs = [&](int t) {
        const float* ga = gA + t * 16;
        float4 a0 = *reinterpret_cast<const float4*>(ga);
        float4 a1 = *reinterpret_cast<const float4*>(ga + 4);
        ar[0]=a0.x; ar[1]=a0.y; ar[2]=a0.z; ar[3]=a0.w;
        ar[4]=a1.x; ar[5]=a1.y; ar[6]=a1.z; ar[7]=a1.w;
        const float* gb = gB + (size_t)(t * 16 + bK) * N;
        float4 b0 = *reinterpret_cast<const float4*>(gb);
        float4 b1 = *reinterpret_cast<const float4*>(gb + 4);
        br[0]=b0.x; br[1]=b0.y; br[2]=b0.z; br[3]=b0.w;
        br[4]=b1.x; br[5]=b1.y; br[6]=b1.z; br[7]=b1.w;
    };

    auto storeTile = [&](int buf) {
        float* as = As2[buf];
        float* bs = Bs2[buf];
        #pragma unroll
        for (int j = 0; j < 8; j++) {
            // A element: row aRow, k = aK8*8 + j
            const int slotA = aLr * 4 + (j & 3);
            const int addrA = (aSbase + (slotA ^ aKey)) * 4 + (j >> 2) * 2 + aHalf;
            as[addrA] = tff(ar[j]);
            // B element: k = bK, col = bCg*8 + j
            const int slotB = j * 4 + bLc;
            const int addrB = (bSbase + (slotB ^ (bCg & 15))) * 2 + bHalf;
            bs[addrB] = tff(br[j]);
        }
    };

    loadRegs(0);
    storeTile(0);
    __syncthreads();

    for (int t = 0; t < T; t++) {
        const int cur = t & 1;
        if (t + 1 < T) loadRegs(t + 1);

        const float* as = As2[cur];
        const float* bs = Bs2[cur];
        #pragma unroll
        for (int k8 = 0; k8 < 2; k8++) {
            float4 af[4];
            float2 bfr[4];
            #pragma unroll
            for (int mt = 0; mt < 4; mt++) {
                const int S = ((warpM * 4 + mt) * 2 + k8);
                af[mt] = *reinterpret_cast<const float4*>(&as[(S * 32 + pslotA) * 4]);
            }
            #pragma unroll
            for (int nt = 0; nt < 4; nt++) {
                const int cg = warpN * 4 + nt;
                const int ps = (lr * 4 + lc) ^ (cg & 15);
                bfr[nt] = *reinterpret_cast<const float2*>(&bs[((cg * 2 + k8) * 32 + ps) * 2]);
            }
            #pragma unroll
            for (int mt = 0; mt < 4; mt++) {
                const uint32_t a0 = __float_as_uint(af[mt].x);
                const uint32_t a1 = __float_as_uint(af[mt].y);
                const uint32_t a2 = __float_as_uint(af[mt].z);
                const uint32_t a3 = __float_as_uint(af[mt].w);
                #pragma unroll
                for (int nt = 0; nt < 4; nt++)
                    mma_tf32(c[mt][nt], a0, a1, a2, a3,
                             __float_as_uint(bfr[nt].x), __float_as_uint(bfr[nt].y));
            }
        }

        if (t + 1 < T) storeTile((t + 1) & 1);
        __syncthreads();
    }

    // epilogue (fragment layout identical to R3/R5 proven mapping)
    #pragma unroll
    for (int mt = 0; mt < 4; mt++) {
        const int r0 = rowBase + warpM * 64 + mt * 16 + lr;
        #pragma unroll
        for (int nt = 0; nt < 4; nt++) {
            const int col = colBase + warpN * 32 + nt * 8 + lc * 2;
            const float b0 = bias[col], b1 = bias[col + 1];
            float v00 = c[mt][nt][0] + b0, v01 = c[mt][nt][1] + b1;
            float v10 = c[mt][nt][2] + b0, v11 = c[mt][nt][3] + b1;
            if (EPI == 1) {
                v00 = fmaxf(v00, 0.f); v01 = fmaxf(v01, 0.f);
                v10 = fmaxf(v10, 0.f); v11 = fmaxf(v11, 0.f);
            }
            if (EPI == 2) {
                const float* p0 = &pe[(size_t)(r0 & (SS - 1)) * N + col];
                const float* p1 = &pe[(size_t)((r0 + 8) & (SS - 1)) * N + col];
                v00 += p0[0]; v01 += p0[1];
                v10 += p1[0]; v11 += p1[1];
            }
            *reinterpret_cast<float2*>(&C[(size_t)r0 * N + col]) = make_float2(v00, v01);
            *reinterpret_cast<float2*>(&C[(size_t)(r0 + 8) * N + col]) = make_float2(v10, v11);
        }
    }
}

// ---------------- fused flash attention (unchanged from R5, proven) ----------
#define KSTR 68
#define VSTR 72

__global__ __launch_bounds__(256)
void fattn_kernel(const float* __restrict__ q, const float* __restrict__ k,
                  const float* __restrict__ v, float* __restrict__ ctx)
{
    __shared__ float KP[64 * KSTR];   // Q staging, then K tile, then P tile
    __shared__ float Vs[64 * VSTR];
    __shared__ float Mred[4][2][16];
    __shared__ float Lred[4][2][16];

    const int tid   = threadIdx.x;
    const int lane  = tid & 31;
    const int warp  = tid >> 5;
    const int warpR = warp >> 1;
    const int warpC = warp & 1;
    const int lr    = lane >> 2;
    const int lc    = lane & 3;

    const int bh = blockIdx.y;
    const int b  = bh >> 4, h = bh & 15;
    const int q0 = blockIdx.x * 64;
    const float* qb = q + (size_t)b * SS * DD + (size_t)h * DKH;
    const float* kb = k + (size_t)b * SS * DD + (size_t)h * DKH;
    const float* vb = v + (size_t)b * SS * DD + (size_t)h * DKH;

    const int lrow = tid >> 2;
    const int lcl  = (tid & 3) * 4;

    {
        const float* qr = qb + (size_t)(q0 + lrow) * DD;
        #pragma unroll
        for (int j = 0; j < 4; j++) {
            float4 t = *reinterpret_cast<const float4*>(qr + lcl + j * 16);
            *reinterpret_cast<float4*>(&KP[lrow * KSTR + lcl + j * 16]) =
                make_float4(tff(t.x), tff(t.y), tff(t.z), tff(t.w));
        }
    }
    __syncthreads();

    const int r0 = warpR * 16 + lr;
    uint32_t qf[8][4];
    #pragma unroll
    for (int kk = 0; kk < 8; kk++) {
        qf[kk][0] = __float_as_uint(KP[(r0)     * KSTR + kk * 8 + lc]);
        qf[kk][1] = __float_as_uint(KP[(r0 + 8) * KSTR + kk * 8 + lc]);
        qf[kk][2] = __float_as_uint(KP[(r0)     * KSTR + kk * 8 + lc + 4]);
        qf[kk][3] = __float_as_uint(KP[(r0 + 8) * KSTR + kk * 8 + lc + 4]);
    }
    __syncthreads();

    float o[4][4];
    #pragma unroll
    for (int nt = 0; nt < 4; nt++)
        #pragma unroll
        for (int i = 0; i < 4; i++) o[nt][i] = 0.f;
    float mrun0 = -INFINITY, mrun1 = -INFINITY;
    float lrun0 = 0.f, lrun1 = 0.f;

    for (int t = 0; t < 16; t++) {
        {
            const float* kr = kb + (size_t)(t * 64 + lrow) * DD;
            const float* vr = vb + (size_t)(t * 64 + lrow) * DD;
            #pragma unroll
            for (int j = 0; j < 4; j++) {
                float4 tk = *reinterpret_cast<const float4*>(kr + lcl + j * 16);
                *reinterpret_cast<float4*>(&KP[lrow * KSTR + lcl + j * 16]) =
                    make_float4(tff(tk.x), tff(tk.y), tff(tk.z), tff(tk.w));
                float4 tv = *reinterpret_cast<const float4*>(vr + lcl + j * 16);
                *reinterpret_cast<float4*>(&Vs[lrow * VSTR + lcl + j * 16]) =
                    make_float4(tff(tv.x), tff(tv.y), tff(tv.z), tff(tv.w));
            }
        }
        __syncthreads();

        float s[4][4];
        #pragma unroll
        for (int nt = 0; nt < 4; nt++)
            #pragma unroll
            for (int i = 0; i < 4; i++) s[nt][i] = 0.f;

        #pragma unroll
        for (int kk = 0; kk < 8; kk++) {
            #pragma unroll
            for (int nt = 0; nt < 4; nt++) {
                const int srow = warpC * 32 + nt * 8 + lr;
                uint32_t b0 = __float_as_uint(KP[srow * KSTR + kk * 8 + lc]);
                uint32_t b1 = __float_as_uint(KP[srow * KSTR + kk * 8 + lc + 4]);
                mma_tf32(s[nt], qf[kk][0], qf[kk][1], qf[kk][2], qf[kk][3], b0, b1);
            }
        }
        #pragma unroll
        for (int nt = 0; nt < 4; nt++)
            #pragma unroll
            for (int i = 0; i < 4; i++) s[nt][i] *= 0.125f;

        float m0 = -INFINITY, m1 = -INFINITY;
        #pragma unroll
        for (int nt = 0; nt < 4; nt++) {
            m0 = fmaxf(m0, fmaxf(s[nt][0], s[nt][1]));
            m1 = fmaxf(m1, fmaxf(s[nt][2], s[nt][3]));
        }
        m0 = fmaxf(m0, __shfl_xor_sync(~0u, m0, 1));
        m0 = fmaxf(m0, __shfl_xor_sync(~0u, m0, 2));
        m1 = fmaxf(m1, __shfl_xor_sync(~0u, m1, 1));
        m1 = fmaxf(m1, __shfl_xor_sync(~0u, m1, 2));
        if (lc == 0) { Mred[warpR][warpC][lr] = m0; Mred[warpR][warpC][lr + 8] = m1; }
        __syncthreads();
        const float mt0 = fmaxf(Mred[warpR][0][lr],     Mred[warpR][1][lr]);
        const float mt1 = fmaxf(Mred[warpR][0][lr + 8], Mred[warpR][1][lr + 8]);

        const float mn0 = fmaxf(mrun0, mt0);
        const float mn1 = fmaxf(mrun1, mt1);
        const float a0 = __expf(mrun0 - mn0);
        const float a1 = __expf(mrun1 - mn1);
        mrun0 = mn0; mrun1 = mn1;

        float ls0 = 0.f, ls1 = 0.f;
        #pragma unroll
        for (int nt = 0; nt < 4; nt++) {
            s[nt][0] = __expf(s[nt][0] - mn0);
            s[nt][1] = __expf(s[nt][1] - mn0);
            s[nt][2] = __expf(s[nt][2] - mn1);
            s[nt][3] = __expf(s[nt][3] - mn1);
            ls0 += s[nt][0] + s[nt][1];
            ls1 += s[nt][2] + s[nt][3];
            const int pc = warpC * 32 + nt * 8 + 2 * lc;
            *reinterpret_cast<float2*>(&KP[(r0)     * KSTR + pc]) =
                make_float2(tff(s[nt][0]), tff(s[nt][1]));
            *reinterpret_cast<float2*>(&KP[(r0 + 8) * KSTR + pc]) =
                make_float2(tff(s[nt][2]), tff(s[nt][3]));
            o[nt][0] *= a0; o[nt][1] *= a0;
            o[nt][2] *= a1; o[nt][3] *= a1;
        }
        ls0 += __shfl_xor_sync(~0u, ls0, 1);
        ls0 += __shfl_xor_sync(~0u, ls0, 2);
        ls1 += __shfl_xor_sync(~0u, ls1, 1);
        ls1 += __shfl_xor_sync(~0u, ls1, 2);
        if (lc == 0) { Lred[warpR][warpC][lr] = ls0; Lred[warpR][warpC][lr + 8] = ls1; }
        __syncthreads();
        lrun0 = lrun0 * a0 + Lred[warpR][0][lr]     + Lred[warpR][1][lr];
        lrun1 = lrun1 * a1 + Lred[warpR][0][lr + 8] + Lred[warpR][1][lr + 8];

        #pragma unroll
        for (int kk = 0; kk < 8; kk++) {
            uint32_t pa0 = __float_as_uint(KP[(r0)     * KSTR + kk * 8 + lc]);
            uint32_t pa1 = __float_as_uint(KP[(r0 + 8) * KSTR + kk * 8 + lc]);
            uint32_t pa2 = __float_as_uint(KP[(r0)     * KSTR + kk * 8 + lc + 4]);
            uint32_t pa3 = __float_as_uint(KP[(r0 + 8) * KSTR + kk * 8 + lc + 4]);
            #pragma unroll
            for (int nt = 0; nt < 4; nt++) {
                const int dcol = warpC * 32 + nt * 8 + lr;
                uint32_t b0 = __float_as_uint(Vs[(kk * 8 + lc)     * VSTR + dcol]);
                uint32_t b1 = __float_as_uint(Vs[(kk * 8 + lc + 4) * VSTR + dcol]);
                mma_tf32(o[nt], pa0, pa1, pa2, pa3, b0, b1);
            }
        }
        __syncthreads();
    }

    const float inv0 = 1.f / lrun0;
    const float inv1 = 1.f / lrun1;
    float* cb = ctx + (size_t)(b * SS + q0) * DD + h * DKH;
    #pragma unroll
    for (int nt = 0; nt < 4; nt++) {
        const int dcol = warpC * 32 + nt * 8 + 2 * lc;
        *reinterpret_cast<float2*>(&cb[(size_t)(r0)     * DD + dcol]) =
            make_float2(o[nt][0] * inv0, o[nt][1] * inv0);
        *reinterpret_cast<float2*>(&cb[(size_t)(r0 + 8) * DD + dcol]) =
            make_float2(o[nt][2] * inv1, o[nt][3] * inv1);
    }
}

// ---------------- x = LayerNorm(x + res) * gamma + beta, in place ----------------
__global__ __launch_bounds__(256)
void add_ln_kernel(float* __restrict__ x, const float* __restrict__ res,
                   const float* __restrict__ gam, const float* __restrict__ bet)
{
    const int row = blockIdx.x;
    const int tid = threadIdx.x;
    float* px = x + (size_t)row * DD;
    const float* pr = res + (size_t)row * DD;

    float4 a = *reinterpret_cast<float4*>(&px[tid*4]);
    float4 r = *reinterpret_cast<const float4*>(&pr[tid*4]);
    a.x += r.x; a.y += r.y; a.z += r.z; a.w += r.w;

    float s  = a.x + a.y + a.z + a.w;
    float sq = a.x*a.x + a.y*a.y + a.z*a.z + a.w*a.w;
    __shared__ float sm[8], sm2[8];
    #pragma unroll
    for (int o = 16; o; o >>= 1) {
        s  += __shfl_xor_sync(~0u, s,  o);
        sq += __shfl_xor_sync(~0u, sq, o);
    }
    if ((tid & 31) == 0) { sm[tid>>5] = s; sm2[tid>>5] = sq; }
    __syncthreads();
    float ts = 0.f, tq = 0.f;
    #pragma unroll
    for (int i = 0; i < 8; i++) { ts += sm[i]; tq += sm2[i]; }
    const float mean = ts * (1.f / DD);
    const float var  = tq * (1.f / DD) - mean * mean;
    const float rstd = rsqrtf(var + EPS);

    float4 g = *reinterpret_cast<const float4*>(&gam[tid*4]);
    float4 b = *reinterpret_cast<const float4*>(&bet[tid*4]);
    float4 o;
    o.x = (a.x - mean) * rstd * g.x + b.x;
    o.y = (a.y - mean) * rstd * g.y + b.y;
    o.z = (a.z - mean) * rstd * g.z + b.z;
    o.w = (a.w - mean) * rstd * g.w + b.w;
    *reinterpret_cast<float4*>(&px[tid*4]) = o;
}

// ---------------- heads ----------------
__global__ __launch_bounds__(256)
void head_kernel(const float* __restrict__ x,
                 const float* __restrict__ phw, const float* __restrict__ phb,
                 const float* __restrict__ vhw, const float* __restrict__ vhb,
                 float* __restrict__ out)
{
    const int o = blockIdx.x;
    const int tid = threadIdx.x;
    float acc = 0.f;
    float biasv;
    if (o < BB * AA) {
        const int b = o / AA, col = o % AA;
        const float* xr = x + (size_t)(b * SS + SS - 1) * DD;
        for (int d = tid; d < DD; d += 256) acc += xr[d] * phw[(size_t)d * AA + col];
        biasv = phb[col];
    } else {
        const int b = o - BB * AA;
        const float* xr = x + (size_t)(b * SS + SS - 1) * DD;
        for (int d = tid; d < DD; d += 256) acc += xr[d] * vhw[d];
        biasv = vhb[0];
    }
    __shared__ float sm[8];
    #pragma unroll
    for (int off = 16; off; off >>= 1) acc += __shfl_xor_sync(~0u, acc, off);
    if ((tid & 31) == 0) sm[tid >> 5] = acc;
    __syncthreads();
    if (tid == 0) {
        float t = 0.f;
        #pragma unroll
        for (int i = 0; i < 8; i++) t += sm[i];
        out[o] = t + biasv;
    }
}

// ---------------- host orchestration ----------------
extern "C" void kernel_launch(void* const* d_in, const int* in_sizes, int n_in,
                              void* d_out, int out_size)
{
    const float* states = (const float*)d_in[0];
    const float* pe     = (const float*)d_in[1];
    const float* emb_w  = (const float*)d_in[2];
    const float* emb_b  = (const float*)d_in[3];
    const float* Wq     = (const float*)d_in[4];
    const float* bq     = (const float*)d_in[5];
    const float* Wk     = (const float*)d_in[6];
    const float* bk     = (const float*)d_in[7];
    const float* Wv     = (const float*)d_in[8];
    const float* bv     = (const float*)d_in[9];
    const float* Wo     = (const float*)d_in[10];
    const float* bo     = (const float*)d_in[11];
    const float* ln1_s  = (const float*)d_in[12];
    const float* ln1_b  = (const float*)d_in[13];
    const float* ln2_s  = (const float*)d_in[14];
    const float* ln2_b  = (const float*)d_in[15];
    const float* ff_w1  = (const float*)d_in[16];
    const float* ff_b1  = (const float*)d_in[17];
    const float* ff_w2  = (const float*)d_in[18];
    const float* ff_b2  = (const float*)d_in[19];
    const float* vh_w   = (const float*)d_in[20];
    const float* vh_b   = (const float*)d_in[21];
    const float* ph_w   = (const float*)d_in[22];
    const float* ph_b   = (const float*)d_in[23];

    float *x, *q, *k, *v, *ctx, *t0, *ff;
    cudaGetSymbolAddress((void**)&x,   g_x);
    cudaGetSymbolAddress((void**)&q,   g_q);
    cudaGetSymbolAddress((void**)&k,   g_k);
    cudaGetSymbolAddress((void**)&v,   g_v);
    cudaGetSymbolAddress((void**)&ctx, g_ctx);
    cudaGetSymbolAddress((void**)&t0,  g_t0);
    cudaGetSymbolAddress((void**)&ff,  g_ff);

    const dim3 gemmD   (DD  / 128, MTOT / 128);   // (8, 32)
    const dim3 gemmFF  (FFD / 128, MTOT / 128);   // (32, 32)
    const dim3 gridAtt (SS / 64, BB * HH);        // (16, 64)

    // embed: x = states @ emb_w + emb_b + pe
    tgemm_kernel<2><<<gemmD, 256>>>(MTOT, DD, SDIM, states, emb_w, emb_b, pe, x);

    for (int l = 0; l < LLAY; l++) {
        const size_t wofD = (size_t)l * DD * DD;
        const size_t wofF = (size_t)l * DD * FFD;

        tgemm_kernel<0><<<gemmD, 256>>>(MTOT, DD, DD, x, Wq + wofD, bq + (size_t)l*DD, nullptr, q);
        tgemm_kernel<0><<<gemmD, 256>>>(MTOT, DD, DD, x, Wk + wofD, bk + (size_t)l*DD, nullptr, k);
        tgemm_kernel<0><<<gemmD, 256>>>(MTOT, DD, DD, x, Wv + wofD, bv + (size_t)l*DD, nullptr, v);

        fattn_kernel<<<gridAtt, 256>>>(q, k, v, ctx);

        tgemm_kernel<0><<<gemmD, 256>>>(MTOT, DD, DD, ctx, Wo + wofD, bo + (size_t)l*DD, nullptr, t0);
        add_ln_kernel<<<MTOT, 256>>>(x, t0, ln1_s + (size_t)l*DD, ln1_b + (size_t)l*DD);

        tgemm_kernel<1><<<gemmFF, 256>>>(MTOT, FFD, DD, x, ff_w1 + wofF, ff_b1 + (size_t)l*FFD, nullptr, ff);
        tgemm_kernel<0><<<gemmD, 256>>>(MTOT, DD, FFD, ff, ff_w2 + wofF, ff_b2 + (size_t)l*DD, nullptr, t0);
        add_ln_kernel<<<MTOT, 256>>>(x, t0, ln2_s + (size_t)l*DD, ln2_b + (size_t)l*DD);
    }

    head_kernel<<<BB * AA + BB, 256>>>(x, ph_w, ph_b, vh_w, vh_b, (float*)d_out);
}

// round 9
// speedup vs baseline: 3.1673x; 1.1259x over previous
#include <cuda_runtime.h>
#include <math.h>
#include <stdint.h>

// ---------------- problem constants ----------------
#define BB   4
#define SS   1024
#define SDIM 512
#define DD   1024
#define HH   16
#define LLAY 6
#define FFD  4096
#define AA   64
#define DKH  64
#define MTOT (BB*SS)          // 4096
#define EPS  1e-5f

// ---------------- scratch ----------------
__device__ float g_x  [MTOT*DD];
__device__ float g_xr [MTOT*DD];          // tf32-rounded x (GEMM A operand)
__device__ float g_q  [MTOT*DD];
__device__ float g_k  [MTOT*DD];
__device__ float g_v  [MTOT*DD];
__device__ float g_ctx[MTOT*DD];
__device__ float g_t0 [MTOT*DD];
__device__ float g_ff [MTOT*FFD];
__device__ float g_sr [MTOT*SDIM];        // rounded states
// rounded weight copies (same layout as originals)
__device__ float g_eWr[SDIM*DD];
__device__ float g_wqr[LLAY*DD*DD];
__device__ float g_wkr[LLAY*DD*DD];
__device__ float g_wvr[LLAY*DD*DD];
__device__ float g_wor[LLAY*DD*DD];
__device__ float g_f1r[(size_t)LLAY*DD*FFD];
__device__ float g_f2r[(size_t)LLAY*DD*FFD];

// ---------------- tf32 helpers ----------------
__device__ __forceinline__ uint32_t f2tf32(float f) {
    uint32_t r;
    asm("cvt.rna.tf32.f32 %0, %1;" : "=r"(r) : "f"(f));
    return r;
}
__device__ __forceinline__ float tff(float f) { return __uint_as_float(f2tf32(f)); }

__device__ __forceinline__ void mma_tf32(float* c,
    uint32_t a0, uint32_t a1, uint32_t a2, uint32_t a3,
    uint32_t b0, uint32_t b1)
{
    asm volatile(
        "mma.sync.aligned.m16n8k8.row.col.f32.tf32.tf32.f32 "
        "{%0,%1,%2,%3}, {%4,%5,%6,%7}, {%8,%9}, {%0,%1,%2,%3};\n"
        : "+f"(c[0]), "+f"(c[1]), "+f"(c[2]), "+f"(c[3])
        : "r"(a0), "r"(a1), "r"(a2), "r"(a3), "r"(b0), "r"(b1));
}

__device__ __forceinline__ void cpa16(uint32_t smem, const void* g) {
    asm volatile("cp.async.cg.shared.global [%0], [%1], 16;\n" :: "r"(smem), "l"(g));
}
__device__ __forceinline__ void cpa_commit() {
    asm volatile("cp.async.commit_group;\n");
}
template<int N>
__device__ __forceinline__ void cpa_wait() {
    asm volatile("cp.async.wait_group %0;\n" :: "n"(N));
}

// ---------------- pipelined tf32 mma.sync GEMM ------------------------------
// C = A[M,K] @ B[K,N] + bias (+epi). Inputs MUST be pre-rounded to tf32.
// EPI: 0 plain fp32, 1 relu+round, 2 +pe dual-write (C fp32, C2 rounded), 3 round.
// 128x128 block, BK=16, 3-stage cp.async ring (48KB smem), 8 warps (2M x 4N),
// warp tile 64x32, one __syncthreads per tile, zero cvt in mainloop.
// A smem: (row,k) -> row*16 + (((k>>2) ^ ((row>>1)&3))<<2) + (k&3)
// B smem: (k,n)   -> k*128  + ((((n>>2) ^ ((k&3)<<1)) & 31)<<2) + (n&3)
template<int EPI>
__global__ __launch_bounds__(256, 2)
void tgemm_kernel(int M, int N, int K,
                  const float* __restrict__ A, const float* __restrict__ Bm,
                  const float* __restrict__ bias, const float* __restrict__ pe,
                  float* __restrict__ C, float* __restrict__ C2)
{
    __shared__ float As[3][2048];
    __shared__ float Bs[3][2048];

    const int tid  = threadIdx.x;
    const int lane = tid & 31;
    const int warp = tid >> 5;
    const int warpM = warp & 1;
    const int warpN = warp >> 1;
    const int lr = lane >> 2;
    const int lc = lane & 3;
    const int m0 = blockIdx.y * 128;
    const int n0 = blockIdx.x * 128;

    // ---- staging maps (each thread: 2 A-chunks + 2 B-chunks of 16B) ----
    const int sRow = tid >> 1;
    const int sCc  = (tid & 1) * 2;
    const int sG   = (sRow >> 1) & 3;
    const int bK   = tid >> 4;
    const int bCn  = (tid & 15) * 2;
    const int bH   = (bK & 3) << 1;

    const float* gA = A + (size_t)(m0 + sRow) * K + sCc * 4;
    const float* gB = Bm + n0 + bCn * 4;

    uint32_t dA0, dA1, dB0, dB1;
    {
        uint32_t baseA = (uint32_t)__cvta_generic_to_shared(&As[0][0]);
        uint32_t baseB = (uint32_t)__cvta_generic_to_shared(&Bs[0][0]);
        dA0 = baseA + (uint32_t)(sRow * 16 + (((sCc + 0) ^ sG) << 2)) * 4u;
        dA1 = baseA + (uint32_t)(sRow * 16 + (((sCc + 1) ^ sG) << 2)) * 4u;
        dB0 = baseB + (uint32_t)(bK * 128 + ((((bCn + 0) ^ bH) & 31) << 2)) * 4u;
        dB1 = baseB + (uint32_t)(bK * 128 + ((((bCn + 1) ^ bH) & 31) << 2)) * 4u;
    }

    auto stage = [&](int t, int s) {
        const uint32_t so = (uint32_t)s * 8192u;
        const float* a = gA + t * 16;
        cpa16(dA0 + so, a);
        cpa16(dA1 + so, a + 4);
        const float* b = gB + (size_t)(t * 16 + bK) * N;
        cpa16(dB0 + so, b);
        cpa16(dB1 + so, b + 4);
        cpa_commit();
    };

    // ---- compute-side constant offsets ----
    const int g = (lr >> 1) & 3;
    int offc[4];
    #pragma unroll
    for (int c = 0; c < 4; c++) offc[c] = ((c ^ g) << 2);
    int rb[4];
    #pragma unroll
    for (int mt = 0; mt < 4; mt++)
        rb[mt] = (warpM * 64 + mt * 16 + lr) * 16 + lc;
    int offB[4];
    #pragma unroll
    for (int nt = 0; nt < 4; nt++) {
        const int ncol = warpN * 32 + nt * 8 + lr;
        offB[nt] = ((((ncol >> 2) ^ (lc << 1)) & 31) << 2) + (lr & 3);
    }
    const int kbase0 = lc * 128;          // k8=0 row base
    const int kbase1 = (8 + lc) * 128;    // k8=8 row base

    float cacc[4][4][4];
    #pragma unroll
    for (int mt = 0; mt < 4; mt++)
        #pragma unroll
        for (int nt = 0; nt < 4; nt++)
            #pragma unroll
            for (int i = 0; i < 4; i++) cacc[mt][nt][i] = 0.f;

    const int T = K >> 4;
    stage(0, 0);
    stage(1, 1);

    for (int t = 0; t < T; t++) {
        const int s = t % 3;
        cpa_wait<1>();
        __syncthreads();
        if (t + 2 < T) stage(t + 2, (t + 2) % 3);

        const float* as = As[s];
        const float* bs = Bs[s];

        uint32_t bf[2][4][2];
        #pragma unroll
        for (int nt = 0; nt < 4; nt++) {
            bf[0][nt][0] = __float_as_uint(bs[kbase0 + offB[nt]]);
            bf[0][nt][1] = __float_as_uint(bs[kbase0 + 512 + offB[nt]]);
        }
        #pragma unroll
        for (int k8i = 0; k8i < 2; k8i++) {
            if (k8i == 0) {
                #pragma unroll
                for (int nt = 0; nt < 4; nt++) {
                    bf[1][nt][0] = __float_as_uint(bs[kbase1 + offB[nt]]);
                    bf[1][nt][1] = __float_as_uint(bs[kbase1 + 512 + offB[nt]]);
                }
            }
            const int oc0 = offc[k8i * 2], oc1 = offc[k8i * 2 + 1];
            #pragma unroll
            for (int mt = 0; mt < 4; mt++) {
                const uint32_t a0 = __float_as_uint(as[rb[mt] + oc0]);
                const uint32_t a2 = __float_as_uint(as[rb[mt] + oc1]);
                const uint32_t a1 = __float_as_uint(as[rb[mt] + 128 + oc0]);
                const uint32_t a3 = __float_as_uint(as[rb[mt] + 128 + oc1]);
                #pragma unroll
                for (int nt = 0; nt < 4; nt++)
                    mma_tf32(cacc[mt][nt], a0, a1, a2, a3,
                             bf[k8i][nt][0], bf[k8i][nt][1]);
            }
        }
    }

    // ---- epilogue (proven R3/R6 fragment mapping) ----
    #pragma unroll
    for (int mt = 0; mt < 4; mt++) {
        const int r0 = m0 + warpM * 64 + mt * 16 + lr;
        #pragma unroll
        for (int nt = 0; nt < 4; nt++) {
            const int col = n0 + warpN * 32 + nt * 8 + lc * 2;
            const float b0 = bias[col], b1 = bias[col + 1];
            float v00 = cacc[mt][nt][0] + b0, v01 = cacc[mt][nt][1] + b1;
            float v10 = cacc[mt][nt][2] + b0, v11 = cacc[mt][nt][3] + b1;
            if (EPI == 1) {
                v00 = tff(fmaxf(v00, 0.f)); v01 = tff(fmaxf(v01, 0.f));
                v10 = tff(fmaxf(v10, 0.f)); v11 = tff(fmaxf(v11, 0.f));
            }
            if (EPI == 3) { v00 = tff(v00); v01 = tff(v01); v10 = tff(v10); v11 = tff(v11); }
            if (EPI == 2) {
                const float* p0 = &pe[(size_t)(r0 & (SS - 1)) * N + col];
                const float* p1 = &pe[(size_t)((r0 + 8) & (SS - 1)) * N + col];
                v00 += p0[0]; v01 += p0[1];
                v10 += p1[0]; v11 += p1[1];
                *reinterpret_cast<float2*>(&C2[(size_t)r0 * N + col]) =
                    make_float2(tff(v00), tff(v01));
                *reinterpret_cast<float2*>(&C2[(size_t)(r0 + 8) * N + col]) =
                    make_float2(tff(v10), tff(v11));
            }
            *reinterpret_cast<float2*>(&C[(size_t)r0 * N + col]) = make_float2(v00, v01);
            *reinterpret_cast<float2*>(&C[(size_t)(r0 + 8) * N + col]) = make_float2(v10, v11);
        }
    }
}

// ---------------- elementwise tf32 round ----------------
__global__ __launch_bounds__(256)
void round_kernel(const float* __restrict__ src, float* __restrict__ dst, int n4)
{
    int i = blockIdx.x * 256 + threadIdx.x;
    if (i < n4) {
        float4 v = reinterpret_cast<const float4*>(src)[i];
        reinterpret_cast<float4*>(dst)[i] =
            make_float4(tff(v.x), tff(v.y), tff(v.z), tff(v.w));
    }
}

// ---------------- fused flash attention (R5-proven; ctx written rounded) -----
#define KSTR 68
#define VSTR 72

__global__ __launch_bounds__(256)
void fattn_kernel(const float* __restrict__ q, const float* __restrict__ k,
                  const float* __restrict__ v, float* __restrict__ ctx)
{
    __shared__ float KP[64 * KSTR];
    __shared__ float Vs[64 * VSTR];
    __shared__ float Mred[4][2][16];
    __shared__ float Lred[4][2][16];

    const int tid   = threadIdx.x;
    const int lane  = tid & 31;
    const int warp  = tid >> 5;
    const int warpR = warp >> 1;
    const int warpC = warp & 1;
    const int lr    = lane >> 2;
    const int lc    = lane & 3;

    const int bh = blockIdx.y;
    const int b  = bh >> 4, h = bh & 15;
    const int q0 = blockIdx.x * 64;
    const float* qb = q + (size_t)b * SS * DD + (size_t)h * DKH;
    const float* kb = k + (size_t)b * SS * DD + (size_t)h * DKH;
    const float* vb = v + (size_t)b * SS * DD + (size_t)h * DKH;

    const int lrow = tid >> 2;
    const int lcl  = (tid & 3) * 4;

    {
        const float* qr = qb + (size_t)(q0 + lrow) * DD;
        #pragma unroll
        for (int j = 0; j < 4; j++) {
            float4 t = *reinterpret_cast<const float4*>(qr + lcl + j * 16);
            *reinterpret_cast<float4*>(&KP[lrow * KSTR + lcl + j * 16]) =
                make_float4(tff(t.x), tff(t.y), tff(t.z), tff(t.w));
        }
    }
    __syncthreads();

    const int r0 = warpR * 16 + lr;
    uint32_t qf[8][4];
    #pragma unroll
    for (int kk = 0; kk < 8; kk++) {
        qf[kk][0] = __float_as_uint(KP[(r0)     * KSTR + kk * 8 + lc]);
        qf[kk][1] = __float_as_uint(KP[(r0 + 8) * KSTR + kk * 8 + lc]);
        qf[kk][2] = __float_as_uint(KP[(r0)     * KSTR + kk * 8 + lc + 4]);
        qf[kk][3] = __float_as_uint(KP[(r0 + 8) * KSTR + kk * 8 + lc + 4]);
    }
    __syncthreads();

    float o[4][4];
    #pragma unroll
    for (int nt = 0; nt < 4; nt++)
        #pragma unroll
        for (int i = 0; i < 4; i++) o[nt][i] = 0.f;
    float mrun0 = -INFINITY, mrun1 = -INFINITY;
    float lrun0 = 0.f, lrun1 = 0.f;

    for (int t = 0; t < 16; t++) {
        {
            const float* kr = kb + (size_t)(t * 64 + lrow) * DD;
            const float* vr = vb + (size_t)(t * 64 + lrow) * DD;
            #pragma unroll
            for (int j = 0; j < 4; j++) {
                float4 tk = *reinterpret_cast<const float4*>(kr + lcl + j * 16);
                *reinterpret_cast<float4*>(&KP[lrow * KSTR + lcl + j * 16]) =
                    make_float4(tff(tk.x), tff(tk.y), tff(tk.z), tff(tk.w));
                float4 tv = *reinterpret_cast<const float4*>(vr + lcl + j * 16);
                *reinterpret_cast<float4*>(&Vs[lrow * VSTR + lcl + j * 16]) =
                    make_float4(tff(tv.x), tff(tv.y), tff(tv.z), tff(tv.w));
            }
        }
        __syncthreads();

        float s[4][4];
        #pragma unroll
        for (int nt = 0; nt < 4; nt++)
            #pragma unroll
            for (int i = 0; i < 4; i++) s[nt][i] = 0.f;

        #pragma unroll
        for (int kk = 0; kk < 8; kk++) {
            #pragma unroll
            for (int nt = 0; nt < 4; nt++) {
                const int srow = warpC * 32 + nt * 8 + lr;
                uint32_t b0 = __float_as_uint(KP[srow * KSTR + kk * 8 + lc]);
                uint32_t b1 = __float_as_uint(KP[srow * KSTR + kk * 8 + lc + 4]);
                mma_tf32(s[nt], qf[kk][0], qf[kk][1], qf[kk][2], qf[kk][3], b0, b1);
            }
        }
        #pragma unroll
        for (int nt = 0; nt < 4; nt++)
            #pragma unroll
            for (int i = 0; i < 4; i++) s[nt][i] *= 0.125f;

        float m0 = -INFINITY, m1 = -INFINITY;
        #pragma unroll
        for (int nt = 0; nt < 4; nt++) {
            m0 = fmaxf(m0, fmaxf(s[nt][0], s[nt][1]));
            m1 = fmaxf(m1, fmaxf(s[nt][2], s[nt][3]));
        }
        m0 = fmaxf(m0, __shfl_xor_sync(~0u, m0, 1));
        m0 = fmaxf(m0, __shfl_xor_sync(~0u, m0, 2));
        m1 = fmaxf(m1, __shfl_xor_sync(~0u, m1, 1));
        m1 = fmaxf(m1, __shfl_xor_sync(~0u, m1, 2));
        if (lc == 0) { Mred[warpR][warpC][lr] = m0; Mred[warpR][warpC][lr + 8] = m1; }
        __syncthreads();
        const float mt0 = fmaxf(Mred[warpR][0][lr],     Mred[warpR][1][lr]);
        const float mt1 = fmaxf(Mred[warpR][0][lr + 8], Mred[warpR][1][lr + 8]);

        const float mn0 = fmaxf(mrun0, mt0);
        const float mn1 = fmaxf(mrun1, mt1);
        const float a0 = __expf(mrun0 - mn0);
        const float a1 = __expf(mrun1 - mn1);
        mrun0 = mn0; mrun1 = mn1;

        float ls0 = 0.f, ls1 = 0.f;
        #pragma unroll
        for (int nt = 0; nt < 4; nt++) {
            s[nt][0] = __expf(s[nt][0] - mn0);
            s[nt][1] = __expf(s[nt][1] - mn0);
            s[nt][2] = __expf(s[nt][2] - mn1);
            s[nt][3] = __expf(s[nt][3] - mn1);
            ls0 += s[nt][0] + s[nt][1];
            ls1 += s[nt][2] + s[nt][3];
            const int pc = warpC * 32 + nt * 8 + 2 * lc;
            *reinterpret_cast<float2*>(&KP[(r0)     * KSTR + pc]) =
                make_float2(tff(s[nt][0]), tff(s[nt][1]));
            *reinterpret_cast<float2*>(&KP[(r0 + 8) * KSTR + pc]) =
                make_float2(tff(s[nt][2]), tff(s[nt][3]));
            o[nt][0] *= a0; o[nt][1] *= a0;
            o[nt][2] *= a1; o[nt][3] *= a1;
        }
        ls0 += __shfl_xor_sync(~0u, ls0, 1);
        ls0 += __shfl_xor_sync(~0u, ls0, 2);
        ls1 += __shfl_xor_sync(~0u, ls1, 1);
        ls1 += __shfl_xor_sync(~0u, ls1, 2);
        if (lc == 0) { Lred[warpR][warpC][lr] = ls0; Lred[warpR][warpC][lr + 8] = ls1; }
        __syncthreads();
        lrun0 = lrun0 * a0 + Lred[warpR][0][lr]     + Lred[warpR][1][lr];
        lrun1 = lrun1 * a1 + Lred[warpR][0][lr + 8] + Lred[warpR][1][lr + 8];

        #pragma unroll
        for (int kk = 0; kk < 8; kk++) {
            uint32_t pa0 = __float_as_uint(KP[(r0)     * KSTR + kk * 8 + lc]);
            uint32_t pa1 = __float_as_uint(KP[(r0 + 8) * KSTR + kk * 8 + lc]);
            uint32_t pa2 = __float_as_uint(KP[(r0)     * KSTR + kk * 8 + lc + 4]);
            uint32_t pa3 = __float_as_uint(KP[(r0 + 8) * KSTR + kk * 8 + lc + 4]);
            #pragma unroll
            for (int nt = 0; nt < 4; nt++) {
                const int dcol = warpC * 32 + nt * 8 + lr;
                uint32_t b0 = __float_as_uint(Vs[(kk * 8 + lc)     * VSTR + dcol]);
                uint32_t b1 = __float_as_uint(Vs[(kk * 8 + lc + 4) * VSTR + dcol]);
                mma_tf32(o[nt], pa0, pa1, pa2, pa3, b0, b1);
            }
        }
        __syncthreads();
    }

    const float inv0 = 1.f / lrun0;
    const float inv1 = 1.f / lrun1;
    float* cb = ctx + (size_t)(b * SS + q0) * DD + h * DKH;
    #pragma unroll
    for (int nt = 0; nt < 4; nt++) {
        const int dcol = warpC * 32 + nt * 8 + 2 * lc;
        *reinterpret_cast<float2*>(&cb[(size_t)(r0)     * DD + dcol]) =
            make_float2(tff(o[nt][0] * inv0), tff(o[nt][1] * inv0));
        *reinterpret_cast<float2*>(&cb[(size_t)(r0 + 8) * DD + dcol]) =
            make_float2(tff(o[nt][2] * inv1), tff(o[nt][3] * inv1));
    }
}

// ---------------- x = LayerNorm(x + res); writes fp32 x and rounded xr -------
__global__ __launch_bounds__(256)
void add_ln_kernel(float* __restrict__ x, const float* __restrict__ res,
                   const float* __restrict__ gam, const float* __restrict__ bet,
                   float* __restrict__ xr)
{
    const int row = blockIdx.x;
    const int tid = threadIdx.x;
    float* px = x + (size_t)row * DD;
    const float* pr = res + (size_t)row * DD;

    float4 a = *reinterpret_cast<float4*>(&px[tid*4]);
    float4 r = *reinterpret_cast<const float4*>(&pr[tid*4]);
    a.x += r.x; a.y += r.y; a.z += r.z; a.w += r.w;

    float s  = a.x + a.y + a.z + a.w;
    float sq = a.x*a.x + a.y*a.y + a.z*a.z + a.w*a.w;
    __shared__ float sm[8], sm2[8];
    #pragma unroll
    for (int o = 16; o; o >>= 1) {
        s  += __shfl_xor_sync(~0u, s,  o);
        sq += __shfl_xor_sync(~0u, sq, o);
    }
    if ((tid & 31) == 0) { sm[tid>>5] = s; sm2[tid>>5] = sq; }
    __syncthreads();
    float ts = 0.f, tq = 0.f;
    #pragma unroll
    for (int i = 0; i < 8; i++) { ts += sm[i]; tq += sm2[i]; }
    const float mean = ts * (1.f / DD);
    const float var  = tq * (1.f / DD) - mean * mean;
    const float rstd = rsqrtf(var + EPS);

    float4 g = *reinterpret_cast<const float4*>(&gam[tid*4]);
    float4 b = *reinterpret_cast<const float4*>(&bet[tid*4]);
    float4 o;
    o.x = (a.x - mean) * rstd * g.x + b.x;
    o.y = (a.y - mean) * rstd * g.y + b.y;
    o.z = (a.z - mean) * rstd * g.z + b.z;
    o.w = (a.w - mean) * rstd * g.w + b.w;
    *reinterpret_cast<float4*>(&px[tid*4]) = o;
    *reinterpret_cast<float4*>(&xr[(size_t)row * DD + tid*4]) =
        make_float4(tff(o.x), tff(o.y), tff(o.z), tff(o.w));
}

// ---------------- heads ----------------
__global__ __launch_bounds__(256)
void head_kernel(const float* __restrict__ x,
                 const float* __restrict__ phw, const float* __restrict__ phb,
                 const float* __restrict__ vhw, const float* __restrict__ vhb,
                 float* __restrict__ out)
{
    const int o = blockIdx.x;
    const int tid = threadIdx.x;
    float acc = 0.f;
    float biasv;
    if (o < BB * AA) {
        const int b = o / AA, col = o % AA;
        const float* xr = x + (size_t)(b * SS + SS - 1) * DD;
        for (int d = tid; d < DD; d += 256) acc += xr[d] * phw[(size_t)d * AA + col];
        biasv = phb[col];
    } else {
        const int b = o - BB * AA;
        const float* xr = x + (size_t)(b * SS + SS - 1) * DD;
        for (int d = tid; d < DD; d += 256) acc += xr[d] * vhw[d];
        biasv = vhb[0];
    }
    __shared__ float sm[8];
    #pragma unroll
    for (int off = 16; off; off >>= 1) acc += __shfl_xor_sync(~0u, acc, off);
    if ((tid & 31) == 0) sm[tid >> 5] = acc;
    __syncthreads();
    if (tid == 0) {
        float t = 0.f;
        #pragma unroll
        for (int i = 0; i < 8; i++) t += sm[i];
        out[o] = t + biasv;
    }
}

// ---------------- host orchestration ----------------
extern "C" void kernel_launch(void* const* d_in, const int* in_sizes, int n_in,
                              void* d_out, int out_size)
{
    const float* states = (const float*)d_in[0];
    const float* pe     = (const float*)d_in[1];
    const float* emb_w  = (const float*)d_in[2];
    const float* emb_b  = (const float*)d_in[3];
    const float* Wq     = (const float*)d_in[4];
    const float* bq     = (const float*)d_in[5];
    const float* Wk     = (const float*)d_in[6];
    const float* bk     = (const float*)d_in[7];
    const float* Wv     = (const float*)d_in[8];
    const float* bv     = (const float*)d_in[9];
    const float* Wo     = (const float*)d_in[10];
    const float* bo     = (const float*)d_in[11];
    const float* ln1_s  = (const float*)d_in[12];
    const float* ln1_b  = (const float*)d_in[13];
    const float* ln2_s  = (const float*)d_in[14];
    const float* ln2_b  = (const float*)d_in[15];
    const float* ff_w1  = (const float*)d_in[16];
    const float* ff_b1  = (const float*)d_in[17];
    const float* ff_w2  = (const float*)d_in[18];
    const float* ff_b2  = (const float*)d_in[19];
    const float* vh_w   = (const float*)d_in[20];
    const float* vh_b   = (const float*)d_in[21];
    const float* ph_w   = (const float*)d_in[22];
    const float* ph_b   = (const float*)d_in[23];

    float *x, *xr, *q, *k, *v, *ctx, *t0, *ff, *sr;
    float *eWr, *wqr, *wkr, *wvr, *wor, *f1r, *f2r;
    cudaGetSymbolAddress((void**)&x,   g_x);
    cudaGetSymbolAddress((void**)&xr,  g_xr);
    cudaGetSymbolAddress((void**)&q,   g_q);
    cudaGetSymbolAddress((void**)&k,   g_k);
    cudaGetSymbolAddress((void**)&v,   g_v);
    cudaGetSymbolAddress((void**)&ctx, g_ctx);
    cudaGetSymbolAddress((void**)&t0,  g_t0);
    cudaGetSymbolAddress((void**)&ff,  g_ff);
    cudaGetSymbolAddress((void**)&sr,  g_sr);
    cudaGetSymbolAddress((void**)&eWr, g_eWr);
    cudaGetSymbolAddress((void**)&wqr, g_wqr);
    cudaGetSymbolAddress((void**)&wkr, g_wkr);
    cudaGetSymbolAddress((void**)&wvr, g_wvr);
    cudaGetSymbolAddress((void**)&wor, g_wor);
    cudaGetSymbolAddress((void**)&f1r, g_f1r);
    cudaGetSymbolAddress((void**)&f2r, g_f2r);

    // ---- prep: tf32-round states + all weights (layouts unchanged) ----
    const int nSt = MTOT * SDIM / 4;
    const int nEm = SDIM * DD / 4;
    const int nWD = LLAY * DD * DD / 4;
    const int nWF = (int)((size_t)LLAY * DD * FFD / 4);
    round_kernel<<<(nSt + 255)/256, 256>>>(states, sr, nSt);
    round_kernel<<<(nEm + 255)/256, 256>>>(emb_w, eWr, nEm);
    round_kernel<<<(nWD + 255)/256, 256>>>(Wq, wqr, nWD);
    round_kernel<<<(nWD + 255)/256, 256>>>(Wk, wkr, nWD);
    round_kernel<<<(nWD + 255)/256, 256>>>(Wv, wvr, nWD);
    round_kernel<<<(nWD + 255)/256, 256>>>(Wo, wor, nWD);
    round_kernel<<<(nWF + 255)/256, 256>>>(ff_w1, f1r, nWF);
    round_kernel<<<(nWF + 255)/256, 256>>>(ff_w2, f2r, nWF);

    const dim3 gemmD (DD  / 128, MTOT / 128);   // (8, 32)
    const dim3 gemmFF(FFD / 128, MTOT / 128);   // (32, 32)
    const dim3 gridAtt(SS / 64, BB * HH);       // (16, 64)

    // embed: x = states @ emb_w + emb_b + pe  (x fp32, xr rounded)
    tgemm_kernel<2><<<gemmD, 256>>>(MTOT, DD, SDIM, sr, eWr, emb_b, pe, x, xr);

    for (int l = 0; l < LLAY; l++) {
        const size_t wofD = (size_t)l * DD * DD;
        const size_t wofF = (size_t)l * DD * FFD;

        tgemm_kernel<3><<<gemmD, 256>>>(MTOT, DD, DD, xr, wqr + wofD, bq + (size_t)l*DD, nullptr, q, nullptr);
        tgemm_kernel<3><<<gemmD, 256>>>(MTOT, DD, DD, xr, wkr + wofD, bk + (size_t)l*DD, nullptr, k, nullptr);
        tgemm_kernel<3><<<gemmD, 256>>>(MTOT, DD, DD, xr, wvr + wofD, bv + (size_t)l*DD, nullptr, v, nullptr);

        fattn_kernel<<<gridAtt, 256>>>(q, k, v, ctx);

        tgemm_kernel<0><<<gemmD, 256>>>(MTOT, DD, DD, ctx, wor + wofD, bo + (size_t)l*DD, nullptr, t0, nullptr);
        add_ln_kernel<<<MTOT, 256>>>(x, t0, ln1_s + (size_t)l*DD, ln1_b + (size_t)l*DD, xr);

        tgemm_kernel<1><<<gemmFF, 256>>>(MTOT, FFD, DD, xr, f1r + wofF, ff_b1 + (size_t)l*FFD, nullptr, ff, nullptr);
        tgemm_kernel<0><<<gemmD, 256>>>(MTOT, DD, FFD, ff, f2r + wofF, ff_b2 + (size_t)l*DD, nullptr, t0, nullptr);
        add_ln_kernel<<<MTOT, 256>>>(x, t0, ln2_s + (size_t)l*DD, ln2_b + (size_t)l*DD, xr);
    }

    head_kernel<<<BB * AA + BB, 256>>>(x, ph_w, ph_b, vh_w, vh_b, (float*)d_out);
}

// round 10
// speedup vs baseline: 3.2126x; 1.0143x over previous
#include <cuda_runtime.h>
#include <math.h>
#include <stdint.h>

// ---------------- problem constants ----------------
#define BB   4
#define SS   1024
#define SDIM 512
#define DD   1024
#define HH   16
#define LLAY 6
#define FFD  4096
#define AA   64
#define DKH  64
#define MTOT (BB*SS)          // 4096
#define EPS  1e-5f
#define QKVN (3*DD)           // 3072

// ---------------- scratch ----------------
__device__ float g_x  [MTOT*DD];
__device__ float g_xr [MTOT*DD];          // tf32-rounded x (GEMM A operand)
__device__ float g_qkv[(size_t)MTOT*QKVN];// fused q|k|v, row stride 3072
__device__ float g_ctx[MTOT*DD];
__device__ float g_t0 [MTOT*DD];
__device__ float g_ff [MTOT*FFD];
__device__ float g_sr [MTOT*SDIM];        // rounded states
// rounded weights
__device__ float g_eWr [SDIM*DD];
__device__ float g_wqkv[(size_t)LLAY*DD*QKVN];  // concat [l][k][sec*1024+n]
__device__ float g_bqkv[LLAY*QKVN];
__device__ float g_wor [LLAY*DD*DD];
__device__ float g_f1r [(size_t)LLAY*DD*FFD];
__device__ float g_f2r [(size_t)LLAY*DD*FFD];

// ---------------- tf32 helpers ----------------
__device__ __forceinline__ uint32_t f2tf32(float f) {
    uint32_t r;
    asm("cvt.rna.tf32.f32 %0, %1;" : "=r"(r) : "f"(f));
    return r;
}
__device__ __forceinline__ float tff(float f) { return __uint_as_float(f2tf32(f)); }

__device__ __forceinline__ void mma_tf32(float* c,
    uint32_t a0, uint32_t a1, uint32_t a2, uint32_t a3,
    uint32_t b0, uint32_t b1)
{
    asm volatile(
        "mma.sync.aligned.m16n8k8.row.col.f32.tf32.tf32.f32 "
        "{%0,%1,%2,%3}, {%4,%5,%6,%7}, {%8,%9}, {%0,%1,%2,%3};\n"
        : "+f"(c[0]), "+f"(c[1]), "+f"(c[2]), "+f"(c[3])
        : "r"(a0), "r"(a1), "r"(a2), "r"(a3), "r"(b0), "r"(b1));
}

__device__ __forceinline__ void cpa16(uint32_t smem, const void* g) {
    asm volatile("cp.async.cg.shared.global [%0], [%1], 16;\n" :: "r"(smem), "l"(g));
}
__device__ __forceinline__ void cpa_commit() {
    asm volatile("cp.async.commit_group;\n");
}
template<int N>
__device__ __forceinline__ void cpa_wait() {
    asm volatile("cp.async.wait_group %0;\n" :: "n"(N));
}

// ---------------- pipelined tf32 mma.sync GEMM (R9-proven, unchanged) --------
// C = A[M,K] @ B[K,N] + bias (+epi). Inputs MUST be pre-rounded to tf32.
// EPI: 0 plain fp32, 1 relu+round, 2 +pe dual-write (C fp32, C2 rounded), 3 round.
template<int EPI>
__global__ __launch_bounds__(256, 2)
void tgemm_kernel(int M, int N, int K,
                  const float* __restrict__ A, const float* __restrict__ Bm,
                  const float* __restrict__ bias, const float* __restrict__ pe,
                  float* __restrict__ C, float* __restrict__ C2)
{
    __shared__ float As[3][2048];
    __shared__ float Bs[3][2048];

    const int tid  = threadIdx.x;
    const int lane = tid & 31;
    const int warp = tid >> 5;
    const int warpM = warp & 1;
    const int warpN = warp >> 1;
    const int lr = lane >> 2;
    const int lc = lane & 3;
    const int m0 = blockIdx.y * 128;
    const int n0 = blockIdx.x * 128;

    const int sRow = tid >> 1;
    const int sCc  = (tid & 1) * 2;
    const int sG   = (sRow >> 1) & 3;
    const int bK   = tid >> 4;
    const int bCn  = (tid & 15) * 2;
    const int bH   = (bK & 3) << 1;

    const float* gA = A + (size_t)(m0 + sRow) * K + sCc * 4;
    const float* gB = Bm + n0 + bCn * 4;

    uint32_t dA0, dA1, dB0, dB1;
    {
        uint32_t baseA = (uint32_t)__cvta_generic_to_shared(&As[0][0]);
        uint32_t baseB = (uint32_t)__cvta_generic_to_shared(&Bs[0][0]);
        dA0 = baseA + (uint32_t)(sRow * 16 + (((sCc + 0) ^ sG) << 2)) * 4u;
        dA1 = baseA + (uint32_t)(sRow * 16 + (((sCc + 1) ^ sG) << 2)) * 4u;
        dB0 = baseB + (uint32_t)(bK * 128 + ((((bCn + 0) ^ bH) & 31) << 2)) * 4u;
        dB1 = baseB + (uint32_t)(bK * 128 + ((((bCn + 1) ^ bH) & 31) << 2)) * 4u;
    }

    auto stage = [&](int t, int s) {
        const uint32_t so = (uint32_t)s * 8192u;
        const float* a = gA + t * 16;
        cpa16(dA0 + so, a);
        cpa16(dA1 + so, a + 4);
        const float* b = gB + (size_t)(t * 16 + bK) * N;
        cpa16(dB0 + so, b);
        cpa16(dB1 + so, b + 4);
        cpa_commit();
    };

    const int g = (lr >> 1) & 3;
    int offc[4];
    #pragma unroll
    for (int c = 0; c < 4; c++) offc[c] = ((c ^ g) << 2);
    int rb[4];
    #pragma unroll
    for (int mt = 0; mt < 4; mt++)
        rb[mt] = (warpM * 64 + mt * 16 + lr) * 16 + lc;
    int offB[4];
    #pragma unroll
    for (int nt = 0; nt < 4; nt++) {
        const int ncol = warpN * 32 + nt * 8 + lr;
        offB[nt] = ((((ncol >> 2) ^ (lc << 1)) & 31) << 2) + (lr & 3);
    }
    const int kbase0 = lc * 128;
    const int kbase1 = (8 + lc) * 128;

    float cacc[4][4][4];
    #pragma unroll
    for (int mt = 0; mt < 4; mt++)
        #pragma unroll
        for (int nt = 0; nt < 4; nt++)
            #pragma unroll
            for (int i = 0; i < 4; i++) cacc[mt][nt][i] = 0.f;

    const int T = K >> 4;
    stage(0, 0);
    stage(1, 1);

    for (int t = 0; t < T; t++) {
        const int s = t % 3;
        cpa_wait<1>();
        __syncthreads();
        if (t + 2 < T) stage(t + 2, (t + 2) % 3);

        const float* as = As[s];
        const float* bs = Bs[s];

        uint32_t bf[2][4][2];
        #pragma unroll
        for (int nt = 0; nt < 4; nt++) {
            bf[0][nt][0] = __float_as_uint(bs[kbase0 + offB[nt]]);
            bf[0][nt][1] = __float_as_uint(bs[kbase0 + 512 + offB[nt]]);
        }
        #pragma unroll
        for (int k8i = 0; k8i < 2; k8i++) {
            if (k8i == 0) {
                #pragma unroll
                for (int nt = 0; nt < 4; nt++) {
                    bf[1][nt][0] = __float_as_uint(bs[kbase1 + offB[nt]]);
                    bf[1][nt][1] = __float_as_uint(bs[kbase1 + 512 + offB[nt]]);
                }
            }
            const int oc0 = offc[k8i * 2], oc1 = offc[k8i * 2 + 1];
            #pragma unroll
            for (int mt = 0; mt < 4; mt++) {
                const uint32_t a0 = __float_as_uint(as[rb[mt] + oc0]);
                const uint32_t a2 = __float_as_uint(as[rb[mt] + oc1]);
                const uint32_t a1 = __float_as_uint(as[rb[mt] + 128 + oc0]);
                const uint32_t a3 = __float_as_uint(as[rb[mt] + 128 + oc1]);
                #pragma unroll
                for (int nt = 0; nt < 4; nt++)
                    mma_tf32(cacc[mt][nt], a0, a1, a2, a3,
                             bf[k8i][nt][0], bf[k8i][nt][1]);
            }
        }
    }

    #pragma unroll
    for (int mt = 0; mt < 4; mt++) {
        const int r0 = m0 + warpM * 64 + mt * 16 + lr;
        #pragma unroll
        for (int nt = 0; nt < 4; nt++) {
            const int col = n0 + warpN * 32 + nt * 8 + lc * 2;
            const float b0 = bias[col], b1 = bias[col + 1];
            float v00 = cacc[mt][nt][0] + b0, v01 = cacc[mt][nt][1] + b1;
            float v10 = cacc[mt][nt][2] + b0, v11 = cacc[mt][nt][3] + b1;
            if (EPI == 1) {
                v00 = tff(fmaxf(v00, 0.f)); v01 = tff(fmaxf(v01, 0.f));
                v10 = tff(fmaxf(v10, 0.f)); v11 = tff(fmaxf(v11, 0.f));
            }
            if (EPI == 3) { v00 = tff(v00); v01 = tff(v01); v10 = tff(v10); v11 = tff(v11); }
            if (EPI == 2) {
                const float* p0 = &pe[(size_t)(r0 & (SS - 1)) * N + col];
                const float* p1 = &pe[(size_t)((r0 + 8) & (SS - 1)) * N + col];
                v00 += p0[0]; v01 += p0[1];
                v10 += p1[0]; v11 += p1[1];
                *reinterpret_cast<float2*>(&C2[(size_t)r0 * N + col]) =
                    make_float2(tff(v00), tff(v01));
                *reinterpret_cast<float2*>(&C2[(size_t)(r0 + 8) * N + col]) =
                    make_float2(tff(v10), tff(v11));
            }
            *reinterpret_cast<float2*>(&C[(size_t)r0 * N + col]) = make_float2(v00, v01);
            *reinterpret_cast<float2*>(&C[(size_t)(r0 + 8) * N + col]) = make_float2(v10, v11);
        }
    }
}

// ---------------- prep 1: concat+round QKV weights and biases ----------------
// weights: [LLAY][DD][3][1024] <- Wq/Wk/Wv [LLAY][DD][1024]; then biases.
#define W4_TOTAL (LLAY * DD * (QKVN / 4))        // 4,718,592 float4
#define B4_TOTAL (LLAY * (QKVN / 4))             // 4,608 float4
__global__ __launch_bounds__(256)
void concat_round_qkv_kernel(const float* __restrict__ Wq, const float* __restrict__ Wk,
                             const float* __restrict__ Wv,
                             const float* __restrict__ bq, const float* __restrict__ bk,
                             const float* __restrict__ bv,
                             float* __restrict__ wqkv, float* __restrict__ bqkv)
{
    const int i = blockIdx.x * 256 + threadIdx.x;
    if (i < W4_TOTAL) {
        const int n4  = i & 255;
        const int sec = (i >> 8) % 3;
        const int k   = (i >> 8) / 3 % DD;
        const int l   = i / (768 * DD);
        const float* src = (sec == 0 ? Wq : sec == 1 ? Wk : Wv)
                           + ((size_t)l * DD + k) * DD + n4 * 4;
        float4 v = *reinterpret_cast<const float4*>(src);
        *reinterpret_cast<float4*>(
            &wqkv[((size_t)l * DD + k) * QKVN + sec * DD + n4 * 4]) =
            make_float4(tff(v.x), tff(v.y), tff(v.z), tff(v.w));
    } else if (i < W4_TOTAL + B4_TOTAL) {
        const int j = i - W4_TOTAL;
        const int n4  = j & 255;
        const int sec = (j >> 8) % 3;
        const int l   = j / 768;
        const float* src = (sec == 0 ? bq : sec == 1 ? bk : bv) + (size_t)l * DD + n4 * 4;
        float4 v = *reinterpret_cast<const float4*>(src);
        *reinterpret_cast<float4*>(&bqkv[(size_t)l * QKVN + sec * DD + n4 * 4]) = v;
    }
}

// ---------------- prep 2: segmented tf32 round (states, emb, Wo, W1, W2) -----
#define SEG0 (MTOT * SDIM / 4)                 // states   524288
#define SEG1 (SDIM * DD / 4)                   // emb      131072
#define SEG2 (LLAY * DD * DD / 4)              // Wo       1572864
#define SEG3 ((int)((size_t)LLAY*DD*FFD/4))    // ff_w1    6291456
#define SEG4 SEG3                              // ff_w2
#define SEGT (SEG0 + SEG1 + SEG2 + SEG3 + SEG4)
__global__ __launch_bounds__(256)
void round_all_kernel(const float* __restrict__ s0, float* __restrict__ d0,
                      const float* __restrict__ s1, float* __restrict__ d1,
                      const float* __restrict__ s2, float* __restrict__ d2,
                      const float* __restrict__ s3, float* __restrict__ d3,
                      const float* __restrict__ s4, float* __restrict__ d4)
{
    int i = blockIdx.x * 256 + threadIdx.x;
    const float* src; float* dst;
    if      (i < SEG0)                        { src = s0; dst = d0; }
    else if ((i -= SEG0) < SEG1)              { src = s1; dst = d1; }
    else if ((i -= SEG1) < SEG2)              { src = s2; dst = d2; }
    else if ((i -= SEG2) < SEG3)              { src = s3; dst = d3; }
    else if ((i -= SEG3) < SEG4)              { src = s4; dst = d4; }
    else return;
    float4 v = reinterpret_cast<const float4*>(src)[i];
    reinterpret_cast<float4*>(dst)[i] =
        make_float4(tff(v.x), tff(v.y), tff(v.z), tff(v.w));
}

// ---------------- fused flash attention (R5-proven; qkv row stride 3072) -----
#define KSTR 68
#define VSTR 72

__global__ __launch_bounds__(256)
void fattn_kernel(const float* __restrict__ qkv, float* __restrict__ ctx)
{
    __shared__ float KP[64 * KSTR];
    __shared__ float Vs[64 * VSTR];
    __shared__ float Mred[4][2][16];
    __shared__ float Lred[4][2][16];

    const int tid   = threadIdx.x;
    const int lane  = tid & 31;
    const int warp  = tid >> 5;
    const int warpR = warp >> 1;
    const int warpC = warp & 1;
    const int lr    = lane >> 2;
    const int lc    = lane & 3;

    const int bh = blockIdx.y;
    const int b  = bh >> 4, h = bh & 15;
    const int q0 = blockIdx.x * 64;
    const float* qb = qkv + (size_t)b * SS * QKVN + (size_t)h * DKH;            // q slice
    const float* kb = qkv + (size_t)b * SS * QKVN + DD + (size_t)h * DKH;       // k slice
    const float* vb = qkv + (size_t)b * SS * QKVN + 2 * DD + (size_t)h * DKH;   // v slice

    const int lrow = tid >> 2;
    const int lcl  = (tid & 3) * 4;

    {
        const float* qr = qb + (size_t)(q0 + lrow) * QKVN;
        #pragma unroll
        for (int j = 0; j < 4; j++) {
            float4 t = *reinterpret_cast<const float4*>(qr + lcl + j * 16);
            *reinterpret_cast<float4*>(&KP[lrow * KSTR + lcl + j * 16]) =
                make_float4(tff(t.x), tff(t.y), tff(t.z), tff(t.w));
        }
    }
    __syncthreads();

    const int r0 = warpR * 16 + lr;
    uint32_t qf[8][4];
    #pragma unroll
    for (int kk = 0; kk < 8; kk++) {
        qf[kk][0] = __float_as_uint(KP[(r0)     * KSTR + kk * 8 + lc]);
        qf[kk][1] = __float_as_uint(KP[(r0 + 8) * KSTR + kk * 8 + lc]);
        qf[kk][2] = __float_as_uint(KP[(r0)     * KSTR + kk * 8 + lc + 4]);
        qf[kk][3] = __float_as_uint(KP[(r0 + 8) * KSTR + kk * 8 + lc + 4]);
    }
    __syncthreads();

    float o[4][4];
    #pragma unroll
    for (int nt = 0; nt < 4; nt++)
        #pragma unroll
        for (int i = 0; i < 4; i++) o[nt][i] = 0.f;
    float mrun0 = -INFINITY, mrun1 = -INFINITY;
    float lrun0 = 0.f, lrun1 = 0.f;

    for (int t = 0; t < 16; t++) {
        {
            const float* kr = kb + (size_t)(t * 64 + lrow) * QKVN;
            const float* vr = vb + (size_t)(t * 64 + lrow) * QKVN;
            #pragma unroll
            for (int j = 0; j < 4; j++) {
                float4 tk = *reinterpret_cast<const float4*>(kr + lcl + j * 16);
                *reinterpret_cast<float4*>(&KP[lrow * KSTR + lcl + j * 16]) =
                    make_float4(tff(tk.x), tff(tk.y), tff(tk.z), tff(tk.w));
                float4 tv = *reinterpret_cast<const float4*>(vr + lcl + j * 16);
                *reinterpret_cast<float4*>(&Vs[lrow * VSTR + lcl + j * 16]) =
                    make_float4(tff(tv.x), tff(tv.y), tff(tv.z), tff(tv.w));
            }
        }
        __syncthreads();

        float s[4][4];
        #pragma unroll
        for (int nt = 0; nt < 4; nt++)
            #pragma unroll
            for (int i = 0; i < 4; i++) s[nt][i] = 0.f;

        #pragma unroll
        for (int kk = 0; kk < 8; kk++) {
            #pragma unroll
            for (int nt = 0; nt < 4; nt++) {
                const int srow = warpC * 32 + nt * 8 + lr;
                uint32_t b0 = __float_as_uint(KP[srow * KSTR + kk * 8 + lc]);
                uint32_t b1 = __float_as_uint(KP[srow * KSTR + kk * 8 + lc + 4]);
                mma_tf32(s[nt], qf[kk][0], qf[kk][1], qf[kk][2], qf[kk][3], b0, b1);
            }
        }
        #pragma unroll
        for (int nt = 0; nt < 4; nt++)
            #pragma unroll
            for (int i = 0; i < 4; i++) s[nt][i] *= 0.125f;

        float m0 = -INFINITY, m1 = -INFINITY;
        #pragma unroll
        for (int nt = 0; nt < 4; nt++) {
            m0 = fmaxf(m0, fmaxf(s[nt][0], s[nt][1]));
            m1 = fmaxf(m1, fmaxf(s[nt][2], s[nt][3]));
        }
        m0 = fmaxf(m0, __shfl_xor_sync(~0u, m0, 1));
        m0 = fmaxf(m0, __shfl_xor_sync(~0u, m0, 2));
        m1 = fmaxf(m1, __shfl_xor_sync(~0u, m1, 1));
        m1 = fmaxf(m1, __shfl_xor_sync(~0u, m1, 2));
        if (lc == 0) { Mred[warpR][warpC][lr] = m0; Mred[warpR][warpC][lr + 8] = m1; }
        __syncthreads();
        const float mt0 = fmaxf(Mred[warpR][0][lr],     Mred[warpR][1][lr]);
        const float mt1 = fmaxf(Mred[warpR][0][lr + 8], Mred[warpR][1][lr + 8]);

        const float mn0 = fmaxf(mrun0, mt0);
        const float mn1 = fmaxf(mrun1, mt1);
        const float a0 = __expf(mrun0 - mn0);
        const float a1 = __expf(mrun1 - mn1);
        mrun0 = mn0; mrun1 = mn1;

        float ls0 = 0.f, ls1 = 0.f;
        #pragma unroll
        for (int nt = 0; nt < 4; nt++) {
            s[nt][0] = __expf(s[nt][0] - mn0);
            s[nt][1] = __expf(s[nt][1] - mn0);
            s[nt][2] = __expf(s[nt][2] - mn1);
            s[nt][3] = __expf(s[nt][3] - mn1);
            ls0 += s[nt][0] + s[nt][1];
            ls1 += s[nt][2] + s[nt][3];
            const int pc = warpC * 32 + nt * 8 + 2 * lc;
            *reinterpret_cast<float2*>(&KP[(r0)     * KSTR + pc]) =
                make_float2(tff(s[nt][0]), tff(s[nt][1]));
            *reinterpret_cast<float2*>(&KP[(r0 + 8) * KSTR + pc]) =
                make_float2(tff(s[nt][2]), tff(s[nt][3]));
            o[nt][0] *= a0; o[nt][1] *= a0;
            o[nt][2] *= a1; o[nt][3] *= a1;
        }
        ls0 += __shfl_xor_sync(~0u, ls0, 1);
        ls0 += __shfl_xor_sync(~0u, ls0, 2);
        ls1 += __shfl_xor_sync(~0u, ls1, 1);
        ls1 += __shfl_xor_sync(~0u, ls1, 2);
        if (lc == 0) { Lred[warpR][warpC][lr] = ls0; Lred[warpR][warpC][lr + 8] = ls1; }
        __syncthreads();
        lrun0 = lrun0 * a0 + Lred[warpR][0][lr]     + Lred[warpR][1][lr];
        lrun1 = lrun1 * a1 + Lred[warpR][0][lr + 8] + Lred[warpR][1][lr + 8];

        #pragma unroll
        for (int kk = 0; kk < 8; kk++) {
            uint32_t pa0 = __float_as_uint(KP[(r0)     * KSTR + kk * 8 + lc]);
            uint32_t pa1 = __float_as_uint(KP[(r0 + 8) * KSTR + kk * 8 + lc]);
            uint32_t pa2 = __float_as_uint(KP[(r0)     * KSTR + kk * 8 + lc + 4]);
            uint32_t pa3 = __float_as_uint(KP[(r0 + 8) * KSTR + kk * 8 + lc + 4]);
            #pragma unroll
            for (int nt = 0; nt < 4; nt++) {
                const int dcol = warpC * 32 + nt * 8 + lr;
                uint32_t b0 = __float_as_uint(Vs[(kk * 8 + lc)     * VSTR + dcol]);
                uint32_t b1 = __float_as_uint(Vs[(kk * 8 + lc + 4) * VSTR + dcol]);
                mma_tf32(o[nt], pa0, pa1, pa2, pa3, b0, b1);
            }
        }
        __syncthreads();
    }

    const float inv0 = 1.f / lrun0;
    const float inv1 = 1.f / lrun1;
    float* cb = ctx + (size_t)(b * SS + q0) * DD + h * DKH;
    #pragma unroll
    for (int nt = 0; nt < 4; nt++) {
        const int dcol = warpC * 32 + nt * 8 + 2 * lc;
        *reinterpret_cast<float2*>(&cb[(size_t)(r0)     * DD + dcol]) =
            make_float2(tff(o[nt][0] * inv0), tff(o[nt][1] * inv0));
        *reinterpret_cast<float2*>(&cb[(size_t)(r0 + 8) * DD + dcol]) =
            make_float2(tff(o[nt][2] * inv1), tff(o[nt][3] * inv1));
    }
}

// ---------------- x = LayerNorm(x + res); writes fp32 x and rounded xr -------
__global__ __launch_bounds__(256)
void add_ln_kernel(float* __restrict__ x, const float* __restrict__ res,
                   const float* __restrict__ gam, const float* __restrict__ bet,
                   float* __restrict__ xr)
{
    const int row = blockIdx.x;
    const int tid = threadIdx.x;
    float* px = x + (size_t)row * DD;
    const float* pr = res + (size_t)row * DD;

    float4 a = *reinterpret_cast<float4*>(&px[tid*4]);
    float4 r = *reinterpret_cast<const float4*>(&pr[tid*4]);
    a.x += r.x; a.y += r.y; a.z += r.z; a.w += r.w;

    float s  = a.x + a.y + a.z + a.w;
    float sq = a.x*a.x + a.y*a.y + a.z*a.z + a.w*a.w;
    __shared__ float sm[8], sm2[8];
    #pragma unroll
    for (int o = 16; o; o >>= 1) {
        s  += __shfl_xor_sync(~0u, s,  o);
        sq += __shfl_xor_sync(~0u, sq, o);
    }
    if ((tid & 31) == 0) { sm[tid>>5] = s; sm2[tid>>5] = sq; }
    __syncthreads();
    float ts = 0.f, tq = 0.f;
    #pragma unroll
    for (int i = 0; i < 8; i++) { ts += sm[i]; tq += sm2[i]; }
    const float mean = ts * (1.f / DD);
    const float var  = tq * (1.f / DD) - mean * mean;
    const float rstd = rsqrtf(var + EPS);

    float4 g = *reinterpret_cast<const float4*>(&gam[tid*4]);
    float4 b = *reinterpret_cast<const float4*>(&bet[tid*4]);
    float4 o;
    o.x = (a.x - mean) * rstd * g.x + b.x;
    o.y = (a.y - mean) * rstd * g.y + b.y;
    o.z = (a.z - mean) * rstd * g.z + b.z;
    o.w = (a.w - mean) * rstd * g.w + b.w;
    *reinterpret_cast<float4*>(&px[tid*4]) = o;
    *reinterpret_cast<float4*>(&xr[(size_t)row * DD + tid*4]) =
        make_float4(tff(o.x), tff(o.y), tff(o.z), tff(o.w));
}

// ---------------- heads ----------------
__global__ __launch_bounds__(256)
void head_kernel(const float* __restrict__ x,
                 const float* __restrict__ phw, const float* __restrict__ phb,
                 const float* __restrict__ vhw, const float* __restrict__ vhb,
                 float* __restrict__ out)
{
    const int o = blockIdx.x;
    const int tid = threadIdx.x;
    float acc = 0.f;
    float biasv;
    if (o < BB * AA) {
        const int b = o / AA, col = o % AA;
        const float* xr = x + (size_t)(b * SS + SS - 1) * DD;
        for (int d = tid; d < DD; d += 256) acc += xr[d] * phw[(size_t)d * AA + col];
        biasv = phb[col];
    } else {
        const int b = o - BB * AA;
        const float* xr = x + (size_t)(b * SS + SS - 1) * DD;
        for (int d = tid; d < DD; d += 256) acc += xr[d] * vhw[d];
        biasv = vhb[0];
    }
    __shared__ float sm[8];
    #pragma unroll
    for (int off = 16; off; off >>= 1) acc += __shfl_xor_sync(~0u, acc, off);
    if ((tid & 31) == 0) sm[tid >> 5] = acc;
    __syncthreads();
    if (tid == 0) {
        float t = 0.f;
        #pragma unroll
        for (int i = 0; i < 8; i++) t += sm[i];
        out[o] = t + biasv;
    }
}

// ---------------- host orchestration ----------------
extern "C" void kernel_launch(void* const* d_in, const int* in_sizes, int n_in,
                              void* d_out, int out_size)
{
    const float* states = (const float*)d_in[0];
    const float* pe     = (const float*)d_in[1];
    const float* emb_w  = (const float*)d_in[2];
    const float* emb_b  = (const float*)d_in[3];
    const float* Wq     = (const float*)d_in[4];
    const float* bq     = (const float*)d_in[5];
    const float* Wk     = (const float*)d_in[6];
    const float* bk     = (const float*)d_in[7];
    const float* Wv     = (const float*)d_in[8];
    const float* bv     = (const float*)d_in[9];
    const float* Wo     = (const float*)d_in[10];
    const float* bo     = (const float*)d_in[11];
    const float* ln1_s  = (const float*)d_in[12];
    const float* ln1_b  = (const float*)d_in[13];
    const float* ln2_s  = (const float*)d_in[14];
    const float* ln2_b  = (const float*)d_in[15];
    const float* ff_w1  = (const float*)d_in[16];
    const float* ff_b1  = (const float*)d_in[17];
    const float* ff_w2  = (const float*)d_in[18];
    const float* ff_b2  = (const float*)d_in[19];
    const float* vh_w   = (const float*)d_in[20];
    const float* vh_b   = (const float*)d_in[21];
    const float* ph_w   = (const float*)d_in[22];
    const float* ph_b   = (const float*)d_in[23];

    float *x, *xr, *qkv, *ctx, *t0, *ff, *sr;
    float *eWr, *wqkv, *bqkv, *wor, *f1r, *f2r;
    cudaGetSymbolAddress((void**)&x,    g_x);
    cudaGetSymbolAddress((void**)&xr,   g_xr);
    cudaGetSymbolAddress((void**)&qkv,  g_qkv);
    cudaGetSymbolAddress((void**)&ctx,  g_ctx);
    cudaGetSymbolAddress((void**)&t0,   g_t0);
    cudaGetSymbolAddress((void**)&ff,   g_ff);
    cudaGetSymbolAddress((void**)&sr,   g_sr);
    cudaGetSymbolAddress((void**)&eWr,  g_eWr);
    cudaGetSymbolAddress((void**)&wqkv, g_wqkv);
    cudaGetSymbolAddress((void**)&bqkv, g_bqkv);
    cudaGetSymbolAddress((void**)&wor,  g_wor);
    cudaGetSymbolAddress((void**)&f1r,  g_f1r);
    cudaGetSymbolAddress((void**)&f2r,  g_f2r);

    // ---- prep (2 launches): QKV concat+round; segmented round of the rest ----
    concat_round_qkv_kernel<<<(W4_TOTAL + B4_TOTAL + 255) / 256, 256>>>(
        Wq, Wk, Wv, bq, bk, bv, wqkv, bqkv);
    round_all_kernel<<<(SEGT + 255) / 256, 256>>>(
        states, sr, emb_w, eWr, Wo, wor, ff_w1, f1r, ff_w2, f2r);

    const dim3 gemmD  (DD   / 128, MTOT / 128);   // (8, 32)
    const dim3 gemmQKV(QKVN / 128, MTOT / 128);   // (24, 32)
    const dim3 gemmFF (FFD  / 128, MTOT / 128);   // (32, 32)
    const dim3 gridAtt(SS / 64, BB * HH);         // (16, 64)

    // embed: x = states @ emb_w + emb_b + pe  (x fp32, xr rounded)
    tgemm_kernel<2><<<gemmD, 256>>>(MTOT, DD, SDIM, sr, eWr, emb_b, pe, x, xr);

    for (int l = 0; l < LLAY; l++) {
        const size_t wofD = (size_t)l * DD * DD;
        const size_t wofF = (size_t)l * DD * FFD;

        // fused QKV projection: one GEMM, N = 3072
        tgemm_kernel<3><<<gemmQKV, 256>>>(MTOT, QKVN, DD, xr,
            wqkv + (size_t)l * DD * QKVN, bqkv + (size_t)l * QKVN, nullptr, qkv, nullptr);

        fattn_kernel<<<gridAtt, 256>>>(qkv, ctx);

        tgemm_kernel<0><<<gemmD, 256>>>(MTOT, DD, DD, ctx, wor + wofD, bo + (size_t)l*DD, nullptr, t0, nullptr);
        add_ln_kernel<<<MTOT, 256>>>(x, t0, ln1_s + (size_t)l*DD, ln1_b + (size_t)l*DD, xr);

        tgemm_kernel<1><<<gemmFF, 256>>>(MTOT, FFD, DD, xr, f1r + wofF, ff_b1 + (size_t)l*FFD, nullptr, ff, nullptr);
        tgemm_kernel<0><<<gemmD, 256>>>(MTOT, DD, FFD, ff, f2r + wofF, ff_b2 + (size_t)l*DD, nullptr, t0, nullptr);
        add_ln_kernel<<<MTOT, 256>>>(x, t0, ln2_s + (size_t)l*DD, ln2_b + (size_t)l*DD, xr);
    }

    head_kernel<<<BB * AA + BB, 256>>>(x, ph_w, ph_b, vh_w, vh_b, (float*)d_out);
}